// round 14
// baseline (speedup 1.0000x reference)
#include <cuda_runtime.h>
#include <cuda_fp16.h>
#include <cstdint>
#include <math.h>

// Problem constants
#define B_  4
#define S_  2048
#define D_  1024
#define BS_ (B_ * S_)          // 8192

// ---------------- scratch (static device globals; no runtime allocation) ----
__device__ __half g_Xh[BS_ * D_], g_Xl[BS_ * D_];        // x hi/lo
__device__ __half g_Yh[BS_ * D_], g_Yl[BS_ * D_];        // y hi/lo
__device__ __half g_Qh[BS_ * D_], g_Ql[BS_ * D_];        // Q hi/lo
__device__ __half g_Khh[BS_ * D_], g_Khl[BS_ * D_];      // Kh hi/lo
__device__ __half g_VTh[BS_ * D_];                       // V^T per batch (fp16)
__device__ __half g_Ph[B_ * S_ * S_];                    // probs (fp16)
__device__ __half g_WrTh[D_ * D_], g_WrTl[D_ * D_];
__device__ __half g_WqTh[D_ * D_], g_WqTl[D_ * D_];
__device__ __half g_WvTh[D_ * D_];
__device__ __half g_WvTl[D_ * D_];                       // kept for convT4 symmetry
__device__ __half g_Wkh[D_ * D_], g_Wkl[D_ * D_];
__device__ __half g_WkrTh[D_ * D_], g_WkrTl[D_ * D_];
__device__ float  g_S[2L * B_ * S_ * S_];  // scores split-K partials (2x64MB)
__device__ float  g_bkr[D_];

// ===========================================================================
__device__ __forceinline__ uint32_t h2u(__half2 h) {
    union { __half2 h; uint32_t u; } c; c.h = h; return c.u;
}

__device__ __forceinline__ void mma16(float* d, const uint32_t* a, const uint32_t* b) {
    asm volatile(
        "mma.sync.aligned.m16n8k16.row.col.f32.f16.f16.f32 "
        "{%0,%1,%2,%3}, {%4,%5,%6,%7}, {%8,%9}, {%0,%1,%2,%3};"
        : "+f"(d[0]), "+f"(d[1]), "+f"(d[2]), "+f"(d[3])
        : "r"(a[0]), "r"(a[1]), "r"(a[2]), "r"(a[3]),
          "r"(b[0]), "r"(b[1]));
}

__device__ __forceinline__ void ldsm4(uint32_t* r, uint32_t addr) {
    asm volatile("ldmatrix.sync.aligned.m8n8.x4.shared.b16 {%0,%1,%2,%3}, [%4];"
        : "=r"(r[0]), "=r"(r[1]), "=r"(r[2]), "=r"(r[3]) : "r"(addr));
}

__device__ __forceinline__ void cpa16(uint32_t dst, const void* src) {
    asm volatile("cp.async.cg.shared.global [%0], [%1], 16;" :: "r"(dst), "l"(src));
}
__device__ __forceinline__ void cpa_commit() {
    asm volatile("cp.async.commit_group;" ::: "memory");
}
__device__ __forceinline__ uint32_t smem_u32(const void* p) {
    uint32_t a;
    asm("{ .reg .u64 t; cvta.to.shared.u64 t, %1; cvt.u32.u64 %0, t; }"
        : "=r"(a) : "l"(p));
    return a;
}

#define ARR_HALFS 4096                       // 128x32 halves = 8KB
#define SM3_BYTES (3 * 4 * ARR_HALFS * 2)    // 96KB (3-product)
#define SMO_BYTES (2 * 32768)                // 64KB (out: BK=64, 2-stage)

// ===========================================================================
// fp16 tensor-core 3-product GEMM (R9-proven config): C[M,N]=op(A@B^T+bias)
// 128x128 block tile, BK=32, 3-stage cp.async, XOR-swizzle, ldmatrix.
// 8 warps (2M x 4N), warp tile 64x32, occ 2.
// ksplit: 0=none (z=batch), 1=z is k-chunk, 2=z=(batch<<1)|khalf.
// ===========================================================================
template<int EPI_COS, int OUT_MODE, int ROW_BIAS>
__global__ __launch_bounds__(256, 2)
void gemmh(const __half* __restrict__ Ah, const __half* __restrict__ Al,
           const __half* __restrict__ Bh, const __half* __restrict__ Bl,
           const float* __restrict__ bias,
           float* __restrict__ C, __half* __restrict__ Ch, __half* __restrict__ Cl,
           int M, int N, int K, int lda, int ldb,
           long sA, long sB, long sC, long sCk, int ksplit)
{
    const int SHB = 4 * ARR_HALFS * 2;
    extern __shared__ __half sm[];
    const uint32_t smb = smem_u32(sm);

    const int z  = blockIdx.z;
    const int zb = (ksplit == 2) ? (z >> 1) : z;
    Ah += (long)zb * sA;  Bh += (long)zb * sB;
    Al += (long)zb * sA;  Bl += (long)zb * sB;
    const long koff = (ksplit == 1) ? (long)z * K
                    : (ksplit == 2) ? (long)(z & 1) * K : 0;
    const long cofs = (ksplit == 2) ? ((long)zb * sC + (long)(z & 1) * sCk)
                    : (ksplit == 1) ? (long)z * sC
                                    : (long)z * sC;

    const int m0 = blockIdx.y * 128;
    const int n0 = blockIdx.x * 128;
    const int t    = threadIdx.x;
    const int lane = t & 31;
    const int w    = t >> 5;
    const int g    = lane >> 2;
    const int tg   = lane & 3;
    const int wm   = w & 1;
    const int wn   = w >> 1;

    const int KT = K / 32;

    auto stage_load = [&](int s, int kt) {
        const long kb = koff + (long)kt * 32;
#pragma unroll
        for (int h = 0; h < 2; ++h) {
            const int c   = t + h * 256;
            const int row = c >> 2, q = c & 3;
            const int pq  = q ^ ((row >> 1) & 3);
            const uint32_t so = smb + (uint32_t)s * SHB + (uint32_t)(row * 32 + pq * 8) * 2;
            const long ga = (long)(m0 + row) * lda + kb + q * 8;
            const long gb = (long)(n0 + row) * ldb + kb + q * 8;
            cpa16(so,         Ah + ga);
            cpa16(so + 8192,  Al + ga);
            cpa16(so + 16384, Bh + gb);
            cpa16(so + 24576, Bl + gb);
        }
        cpa_commit();
    };

    const int sub = lane >> 3, l8 = lane & 7;
    const int a_csel = sub >> 1;
    const int a_moff = (sub & 1) * 8 + l8;
    const int b_csel = sub & 1;
    const int b_noff = (sub >> 1) * 8 + l8;

    uint32_t rA32[4], xqA[4];
#pragma unroll
    for (int mt = 0; mt < 4; ++mt) {
        const int row = wm * 64 + mt * 16 + a_moff;
        rA32[mt] = (uint32_t)row * 32;
        xqA[mt]  = (row >> 1) & 3;
    }
    uint32_t rB32[2], xqB[2];
#pragma unroll
    for (int np = 0; np < 2; ++np) {
        const int row = wn * 32 + np * 16 + b_noff;
        rB32[np] = (uint32_t)row * 32;
        xqB[np]  = (row >> 1) & 3;
    }

    float acc[4][4][4];
#pragma unroll
    for (int i = 0; i < 4; ++i)
#pragma unroll
        for (int j = 0; j < 4; ++j)
#pragma unroll
            for (int r = 0; r < 4; ++r) acc[i][j][r] = 0.f;

    stage_load(0, 0);
    stage_load(1, 1);

    for (int kt = 0; kt < KT; ++kt) {
        asm volatile("cp.async.wait_group 1;" ::: "memory");
        __syncthreads();
        if (kt + 2 < KT) stage_load((kt + 2) % 3, kt + 2);

        const uint32_t sAh = smb + (uint32_t)(kt % 3) * SHB;
        const uint32_t sAl = sAh + 8192;
        const uint32_t sBh = sAh + 16384;
        const uint32_t sBl = sAh + 24576;

#pragma unroll
        for (int ks = 0; ks < 2; ++ks) {
            const uint32_t qa = (uint32_t)(2 * ks + a_csel);
            const uint32_t qb = (uint32_t)(2 * ks + b_csel);

            uint32_t bh[4][2], bl[4][2];
#pragma unroll
            for (int np = 0; np < 2; ++np) {
                const uint32_t off = (rB32[np] + ((qb ^ xqB[np]) << 3)) * 2;
                uint32_t r[4];
                ldsm4(r, sBh + off);
                bh[np * 2][0] = r[0]; bh[np * 2][1] = r[1];
                bh[np * 2 + 1][0] = r[2]; bh[np * 2 + 1][1] = r[3];
                ldsm4(r, sBl + off);
                bl[np * 2][0] = r[0]; bl[np * 2][1] = r[1];
                bl[np * 2 + 1][0] = r[2]; bl[np * 2 + 1][1] = r[3];
            }
#pragma unroll
            for (int mt = 0; mt < 4; ++mt) {
                const uint32_t off = (rA32[mt] + ((qa ^ xqA[mt]) << 3)) * 2;
                uint32_t ah[4], al[4];
                ldsm4(ah, sAh + off);
                ldsm4(al, sAl + off);
#pragma unroll
                for (int nt = 0; nt < 4; ++nt) {
                    mma16(acc[mt][nt], ah, bh[nt]);
                    mma16(acc[mt][nt], al, bh[nt]);
                    mma16(acc[mt][nt], ah, bl[nt]);
                }
            }
        }
    }

#pragma unroll
    for (int mt = 0; mt < 4; ++mt) {
#pragma unroll
        for (int nt = 0; nt < 4; ++nt) {
            const int r0 = m0 + wm * 64 + mt * 16 + g;
            const int c0 = n0 + wn * 32 + nt * 8 + 2 * tg;
            float b00 = 0.f, b01 = 0.f, b10 = 0.f, b11 = 0.f;
            if (bias) {
                if (ROW_BIAS) {
                    b00 = b01 = bias[r0];
                    b10 = b11 = bias[r0 + 8];
                } else {
                    b00 = b10 = bias[c0];
                    b01 = b11 = bias[c0 + 1];
                }
            }
            float v00 = acc[mt][nt][0] + b00;
            float v01 = acc[mt][nt][1] + b01;
            float v10 = acc[mt][nt][2] + b10;
            float v11 = acc[mt][nt][3] + b11;
            if (EPI_COS) {
                v00 = __cosf(v00); v01 = __cosf(v01);
                v10 = __cosf(v10); v11 = __cosf(v11);
            }
            long o0 = cofs + (long)r0 * N + c0;
            long o1 = o0 + 8L * N;
            if (OUT_MODE == 1) {
                __half2 h0 = __floats2half2_rn(v00, v01);
                __half2 h1 = __floats2half2_rn(v10, v11);
                __half2 l0 = __floats2half2_rn(v00 - __low2float(h0), v01 - __high2float(h0));
                __half2 l1 = __floats2half2_rn(v10 - __low2float(h1), v11 - __high2float(h1));
                *(uint32_t*)(Ch + o0) = h2u(h0);
                *(uint32_t*)(Cl + o0) = h2u(l0);
                *(uint32_t*)(Ch + o1) = h2u(h1);
                *(uint32_t*)(Cl + o1) = h2u(l1);
            } else if (OUT_MODE == 2) {
                *(uint32_t*)(Ch + o0) = h2u(__floats2half2_rn(v00, v01));
                *(uint32_t*)(Ch + o1) = h2u(__floats2half2_rn(v10, v11));
            } else {
                *(float2*)(C + o0) = make_float2(v00, v01);
                *(float2*)(C + o1) = make_float2(v10, v11);
            }
        }
    }
}

// ===========================================================================
// Merged Q / Kh / VT launch: 1536 CTAs, segment decode.
//   seg 0: Q  = x @ Wq^T + bq        3-product -> hi/lo, col bias
//   seg 1: Kh = cos(y@Wkr^T + bkr)   3-product -> hi/lo, col bias
//   seg 2: VT[b] = WvT @ y[b]^T + bv PURE fp16 -> hi only, row bias
// ===========================================================================
__global__ __launch_bounds__(256, 2)
void gemmh_qkv(const __half* __restrict__ Xh, const __half* __restrict__ Xl,
               const __half* __restrict__ Yh, const __half* __restrict__ Yl,
               const __half* __restrict__ WqTh, const __half* __restrict__ WqTl,
               const __half* __restrict__ WkrTh, const __half* __restrict__ WkrTl,
               const __half* __restrict__ WvTh,
               const float* __restrict__ bq, const float* __restrict__ bkr,
               const float* __restrict__ bv,
               __half* __restrict__ Qh, __half* __restrict__ Ql,
               __half* __restrict__ Khh, __half* __restrict__ Khl,
               __half* __restrict__ VTh)
{
    const int SHB = 4 * ARR_HALFS * 2;
    extern __shared__ __half sm[];
    const uint32_t smb = smem_u32(sm);

    const int id  = blockIdx.x;
    const int seg = (id >= 1024) ? 2 : (id >> 9);
    const int lid = id - seg * 512;
    const bool p3 = (seg != 2);

    const __half *Ah, *Al, *Bh, *Bl;
    int m0, n0, Ncols;
    long cbase;
    if (seg == 2) {
        const int batch = lid >> 7;
        const int r = lid & 127;
        m0 = (r >> 4) * 128;
        n0 = (r & 15) * 128;
        Ah = WvTh; Al = WvTh;
        Bh = Yh + (long)batch * S_ * D_;
        Bl = Bh;
        Ncols = S_;
        cbase = (long)batch * D_ * S_;
    } else {
        m0 = (lid >> 3) * 128;
        n0 = (lid & 7) * 128;
        if (seg == 0) { Ah = Xh; Al = Xl; Bh = WqTh; Bl = WqTl; }
        else          { Ah = Yh; Al = Yl; Bh = WkrTh; Bl = WkrTl; }
        Ncols = D_;
        cbase = 0;
    }

    const int t    = threadIdx.x;
    const int lane = t & 31;
    const int w    = t >> 5;
    const int g    = lane >> 2;
    const int tg   = lane & 3;
    const int wm   = w & 1;
    const int wn   = w >> 1;

    const int KT = D_ / 32;

    auto stage_load = [&](int s, int kt) {
        const long kb = (long)kt * 32;
#pragma unroll
        for (int h = 0; h < 2; ++h) {
            const int c   = t + h * 256;
            const int row = c >> 2, q = c & 3;
            const int pq  = q ^ ((row >> 1) & 3);
            const uint32_t so = smb + (uint32_t)s * SHB + (uint32_t)(row * 32 + pq * 8) * 2;
            const long ga = (long)(m0 + row) * D_ + kb + q * 8;
            const long gb = (long)(n0 + row) * D_ + kb + q * 8;
            cpa16(so,         Ah + ga);
            cpa16(so + 16384, Bh + gb);
            if (p3) {
                cpa16(so + 8192,  Al + ga);
                cpa16(so + 24576, Bl + gb);
            }
        }
        cpa_commit();
    };

    const int sub = lane >> 3, l8 = lane & 7;
    const int a_csel = sub >> 1;
    const int a_moff = (sub & 1) * 8 + l8;
    const int b_csel = sub & 1;
    const int b_noff = (sub >> 1) * 8 + l8;

    uint32_t rA32[4], xqA[4];
#pragma unroll
    for (int mt = 0; mt < 4; ++mt) {
        const int row = wm * 64 + mt * 16 + a_moff;
        rA32[mt] = (uint32_t)row * 32;
        xqA[mt]  = (row >> 1) & 3;
    }
    uint32_t rB32[2], xqB[2];
#pragma unroll
    for (int np = 0; np < 2; ++np) {
        const int row = wn * 32 + np * 16 + b_noff;
        rB32[np] = (uint32_t)row * 32;
        xqB[np]  = (row >> 1) & 3;
    }

    float acc[4][4][4];
#pragma unroll
    for (int i = 0; i < 4; ++i)
#pragma unroll
        for (int j = 0; j < 4; ++j)
#pragma unroll
            for (int r = 0; r < 4; ++r) acc[i][j][r] = 0.f;

    stage_load(0, 0);
    stage_load(1, 1);

    for (int kt = 0; kt < KT; ++kt) {
        asm volatile("cp.async.wait_group 1;" ::: "memory");
        __syncthreads();
        if (kt + 2 < KT) stage_load((kt + 2) % 3, kt + 2);

        const uint32_t sAh = smb + (uint32_t)(kt % 3) * SHB;
        const uint32_t sAl = sAh + 8192;
        const uint32_t sBh = sAh + 16384;
        const uint32_t sBl = sAh + 24576;

#pragma unroll
        for (int ks = 0; ks < 2; ++ks) {
            const uint32_t qa = (uint32_t)(2 * ks + a_csel);
            const uint32_t qb = (uint32_t)(2 * ks + b_csel);

            uint32_t bh[4][2], bl[4][2];
#pragma unroll
            for (int np = 0; np < 2; ++np) {
                const uint32_t off = (rB32[np] + ((qb ^ xqB[np]) << 3)) * 2;
                uint32_t r[4];
                ldsm4(r, sBh + off);
                bh[np * 2][0] = r[0]; bh[np * 2][1] = r[1];
                bh[np * 2 + 1][0] = r[2]; bh[np * 2 + 1][1] = r[3];
                if (p3) {
                    ldsm4(r, sBl + off);
                    bl[np * 2][0] = r[0]; bl[np * 2][1] = r[1];
                    bl[np * 2 + 1][0] = r[2]; bl[np * 2 + 1][1] = r[3];
                }
            }
#pragma unroll
            for (int mt = 0; mt < 4; ++mt) {
                const uint32_t off = (rA32[mt] + ((qa ^ xqA[mt]) << 3)) * 2;
                uint32_t ah[4], al[4];
                ldsm4(ah, sAh + off);
                if (p3) ldsm4(al, sAl + off);
#pragma unroll
                for (int nt = 0; nt < 4; ++nt) {
                    mma16(acc[mt][nt], ah, bh[nt]);
                    if (p3) {
                        mma16(acc[mt][nt], al, bh[nt]);
                        mma16(acc[mt][nt], ah, bl[nt]);
                    }
                }
            }
        }
    }

    const float* bias = (seg == 0) ? bq : (seg == 1 ? bkr : bv);
    __half* Ch = (seg == 0) ? Qh : (seg == 1 ? Khh : VTh);
    __half* Cl = (seg == 0) ? Ql : Khl;

#pragma unroll
    for (int mt = 0; mt < 4; ++mt) {
#pragma unroll
        for (int nt = 0; nt < 4; ++nt) {
            const int r0 = m0 + wm * 64 + mt * 16 + g;
            const int c0 = n0 + wn * 32 + nt * 8 + 2 * tg;
            float b00, b01, b10, b11;
            if (seg == 2) {
                b00 = b01 = bias[r0];
                b10 = b11 = bias[r0 + 8];
            } else {
                b00 = b10 = bias[c0];
                b01 = b11 = bias[c0 + 1];
            }
            float v00 = acc[mt][nt][0] + b00;
            float v01 = acc[mt][nt][1] + b01;
            float v10 = acc[mt][nt][2] + b10;
            float v11 = acc[mt][nt][3] + b11;
            if (seg == 1) {
                v00 = __cosf(v00); v01 = __cosf(v01);
                v10 = __cosf(v10); v11 = __cosf(v11);
            }
            long o0 = cbase + (long)r0 * Ncols + c0;
            long o1 = o0 + 8L * Ncols;
            __half2 h0 = __floats2half2_rn(v00, v01);
            __half2 h1 = __floats2half2_rn(v10, v11);
            *(uint32_t*)(Ch + o0) = h2u(h0);
            *(uint32_t*)(Ch + o1) = h2u(h1);
            if (seg != 2) {
                __half2 l0 = __floats2half2_rn(v00 - __low2float(h0), v01 - __high2float(h0));
                __half2 l1 = __floats2half2_rn(v10 - __low2float(h1), v11 - __high2float(h1));
                *(uint32_t*)(Cl + o0) = h2u(l0);
                *(uint32_t*)(Cl + o1) = h2u(l1);
            }
        }
    }
}

// ===========================================================================
// out[b] = P[b] @ VT[b]^T — pure fp16, BK=64, 2-stage (R12-proven).
// ===========================================================================
__global__ __launch_bounds__(256, 2)
void gemmh_out(const __half* __restrict__ P, const __half* __restrict__ V,
               float* __restrict__ out)
{
    extern __shared__ __half sm[];
    const uint32_t smb = smem_u32(sm);

    const int z = blockIdx.z;
    P   += (long)z * S_ * S_;
    V   += (long)z * D_ * S_;
    out += (long)z * S_ * D_;

    const int m0 = blockIdx.y * 128;
    const int n0 = blockIdx.x * 128;
    const int t    = threadIdx.x;
    const int lane = t & 31;
    const int w    = t >> 5;
    const int g    = lane >> 2;
    const int tg   = lane & 3;
    const int wm   = w & 1;
    const int wn   = w >> 1;

    const int KT = S_ / 64;

    auto stage_load = [&](int s, int kt) {
        const long kb = (long)kt * 64;
#pragma unroll
        for (int h = 0; h < 4; ++h) {
            const int c   = t + h * 256;
            const int row = c >> 3, q = c & 7;
            const int pq  = q ^ (row & 7);
            const uint32_t so = smb + (uint32_t)s * 32768 + (uint32_t)(row * 64 + pq * 8) * 2;
            cpa16(so,         P + (long)(m0 + row) * S_ + kb + q * 8);
            cpa16(so + 16384, V + (long)(n0 + row) * S_ + kb + q * 8);
        }
        cpa_commit();
    };

    const int sub = lane >> 3, l8 = lane & 7;
    const int a_csel = sub >> 1;
    const int a_moff = (sub & 1) * 8 + l8;
    const int b_csel = sub & 1;
    const int b_noff = (sub >> 1) * 8 + l8;

    uint32_t rA64[4], xqA[4];
#pragma unroll
    for (int mt = 0; mt < 4; ++mt) {
        const int row = wm * 64 + mt * 16 + a_moff;
        rA64[mt] = (uint32_t)row * 64;
        xqA[mt]  = row & 7;
    }
    uint32_t rB64[2], xqB[2];
#pragma unroll
    for (int np = 0; np < 2; ++np) {
        const int row = wn * 32 + np * 16 + b_noff;
        rB64[np] = (uint32_t)row * 64;
        xqB[np]  = row & 7;
    }

    float acc[4][4][4];
#pragma unroll
    for (int i = 0; i < 4; ++i)
#pragma unroll
        for (int j = 0; j < 4; ++j)
#pragma unroll
            for (int r = 0; r < 4; ++r) acc[i][j][r] = 0.f;

    stage_load(0, 0);

    for (int kt = 0; kt < KT; ++kt) {
        asm volatile("cp.async.wait_group 0;" ::: "memory");
        __syncthreads();
        if (kt + 1 < KT) stage_load((kt + 1) & 1, kt + 1);

        const uint32_t sA = smb + (uint32_t)(kt & 1) * 32768;
        const uint32_t sB = sA + 16384;

#pragma unroll
        for (int ks = 0; ks < 4; ++ks) {
            const uint32_t qa = (uint32_t)(2 * ks + a_csel);
            const uint32_t qb = (uint32_t)(2 * ks + b_csel);

            uint32_t bh[4][2];
#pragma unroll
            for (int np = 0; np < 2; ++np) {
                const uint32_t off = (rB64[np] + ((qb ^ xqB[np]) << 3)) * 2;
                uint32_t r[4];
                ldsm4(r, sB + off);
                bh[np * 2][0] = r[0]; bh[np * 2][1] = r[1];
                bh[np * 2 + 1][0] = r[2]; bh[np * 2 + 1][1] = r[3];
            }
#pragma unroll
            for (int mt = 0; mt < 4; ++mt) {
                const uint32_t off = (rA64[mt] + ((qa ^ xqA[mt]) << 3)) * 2;
                uint32_t ah[4];
                ldsm4(ah, sA + off);
#pragma unroll
                for (int nt = 0; nt < 4; ++nt)
                    mma16(acc[mt][nt], ah, bh[nt]);
            }
        }
    }

#pragma unroll
    for (int mt = 0; mt < 4; ++mt) {
#pragma unroll
        for (int nt = 0; nt < 4; ++nt) {
            const int r0 = m0 + wm * 64 + mt * 16 + g;
            const int c0 = n0 + wn * 32 + nt * 8 + 2 * tg;
            long o0 = (long)r0 * D_ + c0;
            *(float2*)(out + o0)            = make_float2(acc[mt][nt][0], acc[mt][nt][1]);
            *(float2*)(out + o0 + 8L * D_)  = make_float2(acc[mt][nt][2], acc[mt][nt][3]);
        }
    }
}

// ===========================================================================
// fp32 -> (hi,lo) fp16 converts
// ===========================================================================
__global__ void conv_xy(const float* __restrict__ x, __half* __restrict__ xh, __half* __restrict__ xl,
                        const float* __restrict__ y, __half* __restrict__ yh, __half* __restrict__ yl)
{
    const float* src = blockIdx.y ? y : x;
    __half* h = blockIdx.y ? yh : xh;
    __half* l = blockIdx.y ? yl : xl;
    const long i = ((long)blockIdx.x * 256 + threadIdx.x) * 4;
    float4 v = *(const float4*)(src + i);
    __half2 h0 = __floats2half2_rn(v.x, v.y);
    __half2 h1 = __floats2half2_rn(v.z, v.w);
    __half2 l0 = __floats2half2_rn(v.x - __low2float(h0), v.y - __high2float(h0));
    __half2 l1 = __floats2half2_rn(v.z - __low2float(h1), v.w - __high2float(h1));
    *(uint2*)(h + i) = make_uint2(h2u(h0), h2u(h1));
    *(uint2*)(l + i) = make_uint2(h2u(l0), h2u(l1));
}

__global__ void conv_hl(const float* __restrict__ src,
                        __half* __restrict__ h, __half* __restrict__ l)
{
    const long i = ((long)blockIdx.x * 256 + threadIdx.x) * 4;
    float4 v = *(const float4*)(src + i);
    __half2 h0 = __floats2half2_rn(v.x, v.y);
    __half2 h1 = __floats2half2_rn(v.z, v.w);
    __half2 l0 = __floats2half2_rn(v.x - __low2float(h0), v.y - __high2float(h0));
    __half2 l1 = __floats2half2_rn(v.z - __low2float(h1), v.w - __high2float(h1));
    *(uint2*)(h + i) = make_uint2(h2u(h0), h2u(h1));
    *(uint2*)(l + i) = make_uint2(h2u(l0), h2u(l1));
}

// ===========================================================================
// Sum 8 split-K fp32 partials -> hi/lo half pair.  D_*D_ elements.
// ===========================================================================
__global__ void combine8(const float* __restrict__ parts,
                         __half* __restrict__ dh, __half* __restrict__ dl)
{
    const long i = ((long)blockIdx.x * 256 + threadIdx.x) * 4;
    const long DD = (long)D_ * D_;
    float4 v = *(const float4*)(parts + i);
#pragma unroll
    for (int p = 1; p < 8; ++p) {
        float4 a = *(const float4*)(parts + p * DD + i);
        v.x += a.x; v.y += a.y; v.z += a.z; v.w += a.w;
    }
    __half2 h0 = __floats2half2_rn(v.x, v.y);
    __half2 h1 = __floats2half2_rn(v.z, v.w);
    __half2 l0 = __floats2half2_rn(v.x - __low2float(h0), v.y - __high2float(h0));
    __half2 l1 = __floats2half2_rn(v.z - __low2float(h1), v.w - __high2float(h1));
    *(uint2*)(dh + i) = make_uint2(h2u(h0), h2u(h1));
    *(uint2*)(dl + i) = make_uint2(h2u(l0), h2u(l1));
}

// ===========================================================================
// Transpose+convert for 3 square weights + bkr GEMV, ONE launch (z selects).
// ===========================================================================
__global__ void convT4(const float* __restrict__ s0, __half* __restrict__ d0h, __half* __restrict__ d0l,
                       const float* __restrict__ s1, __half* __restrict__ d1h, __half* __restrict__ d1l,
                       const float* __restrict__ s2, __half* __restrict__ d2h, __half* __restrict__ d2l,
                       const float* __restrict__ bk, const float* __restrict__ br,
                       float* __restrict__ bkr)
{
    const int x = threadIdx.x, yy = threadIdx.y;   // 32 x 8
    if (blockIdx.z == 3) {
        const int r = blockIdx.y * 32 + blockIdx.x;
        const int t = yy * 32 + x;
        float s = 0.f;
        for (int d = t; d < D_; d += 256)
            s += bk[d] * s0[(long)d * D_ + r];    // s0 = Wr
#pragma unroll
        for (int o = 16; o > 0; o >>= 1) s += __shfl_xor_sync(0xffffffffu, s, o);
        __shared__ float red[8];
        if ((t & 31) == 0) red[t >> 5] = s;
        __syncthreads();
        if (t == 0) {
            float ss = br[r];
            for (int i = 0; i < 8; ++i) ss += red[i];
            bkr[r] = ss;
        }
        return;
    }

    __shared__ float tile[32][33];
    const float* src; __half *dh, *dl;
    if (blockIdx.z == 0)      { src = s0; dh = d0h; dl = d0l; }
    else if (blockIdx.z == 1) { src = s1; dh = d1h; dl = d1l; }
    else                      { src = s2; dh = d2h; dl = d2l; }

    const int c0 = blockIdx.x * 32, r0 = blockIdx.y * 32;
#pragma unroll
    for (int j = 0; j < 32; j += 8)
        tile[yy + j][x] = src[(long)(r0 + yy + j) * D_ + c0 + x];
    __syncthreads();
#pragma unroll
    for (int j = 0; j < 32; j += 8) {
        float v = tile[x][yy + j];
        __half hh = __float2half_rn(v);
        long o = (long)(c0 + yy + j) * D_ + r0 + x;
        dh[o] = hh;
        dl[o] = __float2half_rn(v - __half2float(hh));
    }
}

// ---------------------------------------------------------------------------
// Row softmax over 2048 cols, summing two split-K partial buffers; fp16 out.
__global__ void softmax_rows2(const float* __restrict__ s0,
                              const float* __restrict__ s1,
                              __half* __restrict__ ph)
{
    const int NCOL = S_;
    const long ro = (long)blockIdx.x * NCOL;
    const int t = threadIdx.x;
    const int c8 = t * 8;

    __shared__ float red[8];

    float4 a0 = *(const float4*)(s0 + ro + c8);
    float4 a1 = *(const float4*)(s0 + ro + c8 + 4);
    float4 b0 = *(const float4*)(s1 + ro + c8);
    float4 b1 = *(const float4*)(s1 + ro + c8 + 4);
    float v[8] = { a0.x + b0.x, a0.y + b0.y, a0.z + b0.z, a0.w + b0.w,
                   a1.x + b1.x, a1.y + b1.y, a1.z + b1.z, a1.w + b1.w };

    float mx = v[0];
#pragma unroll
    for (int i = 1; i < 8; ++i) mx = fmaxf(mx, v[i]);
#pragma unroll
    for (int o = 16; o > 0; o >>= 1) mx = fmaxf(mx, __shfl_xor_sync(0xffffffffu, mx, o));
    if ((t & 31) == 0) red[t >> 5] = mx;
    __syncthreads();
    if (t == 0) {
        float m = red[0];
        for (int i = 1; i < 8; ++i) m = fmaxf(m, red[i]);
        red[0] = m;
    }
    __syncthreads();
    mx = red[0];

    float s = 0.f;
#pragma unroll
    for (int i = 0; i < 8; ++i) { v[i] = __expf(v[i] - mx); s += v[i]; }
#pragma unroll
    for (int o = 16; o > 0; o >>= 1) s += __shfl_xor_sync(0xffffffffu, s, o);
    __syncthreads();
    if ((t & 31) == 0) red[t >> 5] = s;
    __syncthreads();
    if (t == 0) {
        float ss = 0.f;
        for (int i = 0; i < 8; ++i) ss += red[i];
        red[0] = 1.f / ss;
    }
    __syncthreads();
    const float inv = red[0];

    uint32_t hw[4];
#pragma unroll
    for (int i = 0; i < 4; ++i)
        hw[i] = h2u(__floats2half2_rn(v[2 * i] * inv, v[2 * i + 1] * inv));
    *(uint4*)(ph + ro + c8) = make_uint4(hw[0], hw[1], hw[2], hw[3]);
}

// ---------------------------------------------------------------------------
extern "C" void kernel_launch(void* const* d_in, const int* in_sizes, int n_in,
                              void* d_out, int out_size)
{
    const float* x  = (const float*)d_in[0];
    const float* y  = (const float*)d_in[1];
    const float* Wq = (const float*)d_in[2];
    const float* bq = (const float*)d_in[3];
    const float* Wk = (const float*)d_in[4];
    const float* bk = (const float*)d_in[5];
    const float* Wv = (const float*)d_in[6];
    const float* bv = (const float*)d_in[7];
    const float* Wr = (const float*)d_in[8];
    const float* br = (const float*)d_in[9];
    float* out = (float*)d_out;

    __half *Xh, *Xl, *Yh, *Yl, *Qh, *Ql, *Khh, *Khl, *VTh, *Ph;
    __half *WrTh, *WrTl, *WqTh, *WqTl, *WvTh, *WvTl, *Wkh, *Wkl, *WkrTh, *WkrTl;
    float *Sc, *bkr;
    cudaGetSymbolAddress((void**)&Xh, g_Xh);   cudaGetSymbolAddress((void**)&Xl, g_Xl);
    cudaGetSymbolAddress((void**)&Yh, g_Yh);   cudaGetSymbolAddress((void**)&Yl, g_Yl);
    cudaGetSymbolAddress((void**)&Qh, g_Qh);   cudaGetSymbolAddress((void**)&Ql, g_Ql);
    cudaGetSymbolAddress((void**)&Khh, g_Khh); cudaGetSymbolAddress((void**)&Khl, g_Khl);
    cudaGetSymbolAddress((void**)&VTh, g_VTh);
    cudaGetSymbolAddress((void**)&Ph, g_Ph);
    cudaGetSymbolAddress((void**)&WrTh, g_WrTh); cudaGetSymbolAddress((void**)&WrTl, g_WrTl);
    cudaGetSymbolAddress((void**)&WqTh, g_WqTh); cudaGetSymbolAddress((void**)&WqTl, g_WqTl);
    cudaGetSymbolAddress((void**)&WvTh, g_WvTh); cudaGetSymbolAddress((void**)&WvTl, g_WvTl);
    cudaGetSymbolAddress((void**)&Wkh, g_Wkh);   cudaGetSymbolAddress((void**)&Wkl, g_Wkl);
    cudaGetSymbolAddress((void**)&WkrTh, g_WkrTh); cudaGetSymbolAddress((void**)&WkrTl, g_WkrTl);
    cudaGetSymbolAddress((void**)&Sc, g_S);
    cudaGetSymbolAddress((void**)&bkr, g_bkr);

    cudaFuncSetAttribute(gemmh<0,0,0>, cudaFuncAttributeMaxDynamicSharedMemorySize, SM3_BYTES);
    cudaFuncSetAttribute(gemmh_qkv, cudaFuncAttributeMaxDynamicSharedMemorySize, SM3_BYTES);
    cudaFuncSetAttribute(gemmh_out, cudaFuncAttributeMaxDynamicSharedMemorySize, SMO_BYTES);

    const long SBATCH = (long)S_ * S_;
    const long SHALF  = (long)B_ * S_ * S_;

    // 1) convert inputs / weights (+ bkr fused into convT4 z=3)
    {
        dim3 g(BS_ * D_ / 1024, 2, 1);
        conv_xy<<<g, 256>>>(x, Xh, Xl, y, Yh, Yl);
    }
    conv_hl<<<D_ * D_ / 1024, 256>>>(Wk, Wkh, Wkl);
    {
        dim3 g(D_ / 32, D_ / 32, 4);
        convT4<<<g, dim3(32, 8)>>>(Wr, WrTh, WrTl, Wq, WqTh, WqTl, Wv, WvTh, WvTl,
                                   bk, br, bkr);
    }

    // 2) WkrT = Wr^T @ Wk^T, split-K x8 into fp32 partials (in Sc scratch)
    {
        dim3 g(D_ / 128, D_ / 128, 8);
        gemmh<0,0,0><<<g, 256, SM3_BYTES>>>(WrTh, WrTl, Wkh, Wkl, nullptr,
                                            Sc, nullptr, nullptr,
                                            D_, D_, D_ / 8, D_, D_,
                                            0, 0, (long)D_ * D_, 0, 1);
    }
    combine8<<<D_ * D_ / 1024, 256>>>(Sc, WkrTh, WkrTl);

    // 3) merged Q + Kh + VT (1536 CTAs; VT pure fp16)
    gemmh_qkv<<<1536, 256, SM3_BYTES>>>(Xh, Xl, Yh, Yl,
                                        WqTh, WqTl, WkrTh, WkrTl, WvTh,
                                        bq, bkr, bv,
                                        Qh, Ql, Khh, Khl, VTh);

    // 4) scores[b] = Q[b] @ Kh[b]^T, split-K x2 -> two fp32 partial buffers
    {
        dim3 g(S_ / 128, S_ / 128, 2 * B_);
        gemmh<0,0,0><<<g, 256, SM3_BYTES>>>(Qh, Ql, Khh, Khl, nullptr,
                                            Sc, nullptr, nullptr,
                                            S_, S_, D_ / 2, D_, D_,
                                            (long)S_ * D_, (long)S_ * D_,
                                            SBATCH, SHALF, 2);
    }

    // 5) softmax rows (sums the two partials) -> probs fp16
    softmax_rows2<<<B_ * S_, 256>>>(Sc, Sc + SHALF, Ph);

    // 6) out[b] = P[b] @ VT[b]^T, pure fp16 BK=64 -> fp32
    {
        dim3 g(D_ / 128, S_ / 128, B_);
        gemmh_out<<<g, 256, SMO_BYTES>>>(Ph, VTh, out);
    }
}

// round 15
// speedup vs baseline: 1.0002x; 1.0002x over previous
#include <cuda_runtime.h>
#include <cuda_fp16.h>
#include <cstdint>
#include <math.h>

// Problem constants
#define B_  4
#define S_  2048
#define D_  1024
#define BS_ (B_ * S_)          // 8192

// ---------------- scratch (static device globals; no runtime allocation) ----
__device__ __half g_Xh[BS_ * D_], g_Xl[BS_ * D_];        // x hi/lo
__device__ __half g_Yh[BS_ * D_], g_Yl[BS_ * D_];        // y hi/lo
__device__ __half g_Qh[BS_ * D_], g_Ql[BS_ * D_];        // Q hi/lo
__device__ __half g_Khh[BS_ * D_], g_Khl[BS_ * D_];      // Kh hi/lo
__device__ __half g_VTh[BS_ * D_];                       // V^T per batch (fp16)
__device__ __half g_Ph[B_ * S_ * S_];                    // probs (fp16)
__device__ __half g_WrTh[D_ * D_], g_WrTl[D_ * D_];
__device__ __half g_WqTh[D_ * D_], g_WqTl[D_ * D_];
__device__ __half g_WvTh[D_ * D_];
__device__ __half g_WvTl[D_ * D_];                       // kept for convT4 symmetry
__device__ __half g_Wkh[D_ * D_], g_Wkl[D_ * D_];
__device__ __half g_WkrTh[D_ * D_], g_WkrTl[D_ * D_];
__device__ float  g_S[2L * B_ * S_ * S_];  // scores split-K partials (2x64MB)
__device__ float  g_bkr[D_];

// ===========================================================================
__device__ __forceinline__ uint32_t h2u(__half2 h) {
    union { __half2 h; uint32_t u; } c; c.h = h; return c.u;
}

__device__ __forceinline__ void mma16(float* d, const uint32_t* a, const uint32_t* b) {
    asm volatile(
        "mma.sync.aligned.m16n8k16.row.col.f32.f16.f16.f32 "
        "{%0,%1,%2,%3}, {%4,%5,%6,%7}, {%8,%9}, {%0,%1,%2,%3};"
        : "+f"(d[0]), "+f"(d[1]), "+f"(d[2]), "+f"(d[3])
        : "r"(a[0]), "r"(a[1]), "r"(a[2]), "r"(a[3]),
          "r"(b[0]), "r"(b[1]));
}

__device__ __forceinline__ void ldsm4(uint32_t* r, uint32_t addr) {
    asm volatile("ldmatrix.sync.aligned.m8n8.x4.shared.b16 {%0,%1,%2,%3}, [%4];"
        : "=r"(r[0]), "=r"(r[1]), "=r"(r[2]), "=r"(r[3]) : "r"(addr));
}

__device__ __forceinline__ void cpa16(uint32_t dst, const void* src) {
    asm volatile("cp.async.cg.shared.global [%0], [%1], 16;" :: "r"(dst), "l"(src));
}
__device__ __forceinline__ void cpa_commit() {
    asm volatile("cp.async.commit_group;" ::: "memory");
}
__device__ __forceinline__ uint32_t smem_u32(const void* p) {
    uint32_t a;
    asm("{ .reg .u64 t; cvta.to.shared.u64 t, %1; cvt.u32.u64 %0, t; }"
        : "=r"(a) : "l"(p));
    return a;
}

#define ARR_HALFS 4096                       // 128x32 halves = 8KB
#define SM3_BYTES (3 * 4 * ARR_HALFS * 2)    // 96KB (3-product)
#define SMO_BYTES (2 * 32768)                // 64KB (out: BK=64, 2-stage)

// ===========================================================================
// fp16 tensor-core 3-product GEMM (R9-proven config): C[M,N]=op(A@B^T+bias)
// 128x128 block tile, BK=32, 3-stage cp.async, XOR-swizzle, ldmatrix.
// 8 warps (2M x 4N), warp tile 64x32, occ 2.
// ksplit: 0=none (z=batch), 1=z is k-chunk, 2=z=(batch<<1)|khalf.
// ===========================================================================
template<int EPI_COS, int OUT_MODE, int ROW_BIAS>
__global__ __launch_bounds__(256, 2)
void gemmh(const __half* __restrict__ Ah, const __half* __restrict__ Al,
           const __half* __restrict__ Bh, const __half* __restrict__ Bl,
           const float* __restrict__ bias,
           float* __restrict__ C, __half* __restrict__ Ch, __half* __restrict__ Cl,
           int M, int N, int K, int lda, int ldb,
           long sA, long sB, long sC, long sCk, int ksplit)
{
    const int SHB = 4 * ARR_HALFS * 2;
    extern __shared__ __half sm[];
    const uint32_t smb = smem_u32(sm);

    const int z  = blockIdx.z;
    const int zb = (ksplit == 2) ? (z >> 1) : z;
    Ah += (long)zb * sA;  Bh += (long)zb * sB;
    Al += (long)zb * sA;  Bl += (long)zb * sB;
    const long koff = (ksplit == 1) ? (long)z * K
                    : (ksplit == 2) ? (long)(z & 1) * K : 0;
    const long cofs = (ksplit == 2) ? ((long)zb * sC + (long)(z & 1) * sCk)
                                    : (long)z * sC;

    const int m0 = blockIdx.y * 128;
    const int n0 = blockIdx.x * 128;
    const int t    = threadIdx.x;
    const int lane = t & 31;
    const int w    = t >> 5;
    const int g    = lane >> 2;
    const int tg   = lane & 3;
    const int wm   = w & 1;
    const int wn   = w >> 1;

    const int KT = K / 32;

    auto stage_load = [&](int s, int kt) {
        const long kb = koff + (long)kt * 32;
#pragma unroll
        for (int h = 0; h < 2; ++h) {
            const int c   = t + h * 256;
            const int row = c >> 2, q = c & 3;
            const int pq  = q ^ ((row >> 1) & 3);
            const uint32_t so = smb + (uint32_t)s * SHB + (uint32_t)(row * 32 + pq * 8) * 2;
            const long ga = (long)(m0 + row) * lda + kb + q * 8;
            const long gb = (long)(n0 + row) * ldb + kb + q * 8;
            cpa16(so,         Ah + ga);
            cpa16(so + 8192,  Al + ga);
            cpa16(so + 16384, Bh + gb);
            cpa16(so + 24576, Bl + gb);
        }
        cpa_commit();
    };

    const int sub = lane >> 3, l8 = lane & 7;
    const int a_csel = sub >> 1;
    const int a_moff = (sub & 1) * 8 + l8;
    const int b_csel = sub & 1;
    const int b_noff = (sub >> 1) * 8 + l8;

    uint32_t rA32[4], xqA[4];
#pragma unroll
    for (int mt = 0; mt < 4; ++mt) {
        const int row = wm * 64 + mt * 16 + a_moff;
        rA32[mt] = (uint32_t)row * 32;
        xqA[mt]  = (row >> 1) & 3;
    }
    uint32_t rB32[2], xqB[2];
#pragma unroll
    for (int np = 0; np < 2; ++np) {
        const int row = wn * 32 + np * 16 + b_noff;
        rB32[np] = (uint32_t)row * 32;
        xqB[np]  = (row >> 1) & 3;
    }

    float acc[4][4][4];
#pragma unroll
    for (int i = 0; i < 4; ++i)
#pragma unroll
        for (int j = 0; j < 4; ++j)
#pragma unroll
            for (int r = 0; r < 4; ++r) acc[i][j][r] = 0.f;

    stage_load(0, 0);
    stage_load(1, 1);

    for (int kt = 0; kt < KT; ++kt) {
        asm volatile("cp.async.wait_group 1;" ::: "memory");
        __syncthreads();
        if (kt + 2 < KT) stage_load((kt + 2) % 3, kt + 2);

        const uint32_t sAh = smb + (uint32_t)(kt % 3) * SHB;
        const uint32_t sAl = sAh + 8192;
        const uint32_t sBh = sAh + 16384;
        const uint32_t sBl = sAh + 24576;

#pragma unroll
        for (int ks = 0; ks < 2; ++ks) {
            const uint32_t qa = (uint32_t)(2 * ks + a_csel);
            const uint32_t qb = (uint32_t)(2 * ks + b_csel);

            uint32_t bh[4][2], bl[4][2];
#pragma unroll
            for (int np = 0; np < 2; ++np) {
                const uint32_t off = (rB32[np] + ((qb ^ xqB[np]) << 3)) * 2;
                uint32_t r[4];
                ldsm4(r, sBh + off);
                bh[np * 2][0] = r[0]; bh[np * 2][1] = r[1];
                bh[np * 2 + 1][0] = r[2]; bh[np * 2 + 1][1] = r[3];
                ldsm4(r, sBl + off);
                bl[np * 2][0] = r[0]; bl[np * 2][1] = r[1];
                bl[np * 2 + 1][0] = r[2]; bl[np * 2 + 1][1] = r[3];
            }
#pragma unroll
            for (int mt = 0; mt < 4; ++mt) {
                const uint32_t off = (rA32[mt] + ((qa ^ xqA[mt]) << 3)) * 2;
                uint32_t ah[4], al[4];
                ldsm4(ah, sAh + off);
                ldsm4(al, sAl + off);
#pragma unroll
                for (int nt = 0; nt < 4; ++nt) {
                    mma16(acc[mt][nt], ah, bh[nt]);
                    mma16(acc[mt][nt], al, bh[nt]);
                    mma16(acc[mt][nt], ah, bl[nt]);
                }
            }
        }
    }

#pragma unroll
    for (int mt = 0; mt < 4; ++mt) {
#pragma unroll
        for (int nt = 0; nt < 4; ++nt) {
            const int r0 = m0 + wm * 64 + mt * 16 + g;
            const int c0 = n0 + wn * 32 + nt * 8 + 2 * tg;
            float b00 = 0.f, b01 = 0.f, b10 = 0.f, b11 = 0.f;
            if (bias) {
                if (ROW_BIAS) {
                    b00 = b01 = bias[r0];
                    b10 = b11 = bias[r0 + 8];
                } else {
                    b00 = b10 = bias[c0];
                    b01 = b11 = bias[c0 + 1];
                }
            }
            float v00 = acc[mt][nt][0] + b00;
            float v01 = acc[mt][nt][1] + b01;
            float v10 = acc[mt][nt][2] + b10;
            float v11 = acc[mt][nt][3] + b11;
            if (EPI_COS) {
                v00 = __cosf(v00); v01 = __cosf(v01);
                v10 = __cosf(v10); v11 = __cosf(v11);
            }
            long o0 = cofs + (long)r0 * N + c0;
            long o1 = o0 + 8L * N;
            if (OUT_MODE == 1) {
                __half2 h0 = __floats2half2_rn(v00, v01);
                __half2 h1 = __floats2half2_rn(v10, v11);
                __half2 l0 = __floats2half2_rn(v00 - __low2float(h0), v01 - __high2float(h0));
                __half2 l1 = __floats2half2_rn(v10 - __low2float(h1), v11 - __high2float(h1));
                *(uint32_t*)(Ch + o0) = h2u(h0);
                *(uint32_t*)(Cl + o0) = h2u(l0);
                *(uint32_t*)(Ch + o1) = h2u(h1);
                *(uint32_t*)(Cl + o1) = h2u(l1);
            } else if (OUT_MODE == 2) {
                *(uint32_t*)(Ch + o0) = h2u(__floats2half2_rn(v00, v01));
                *(uint32_t*)(Ch + o1) = h2u(__floats2half2_rn(v10, v11));
            } else {
                *(float2*)(C + o0) = make_float2(v00, v01);
                *(float2*)(C + o1) = make_float2(v10, v11);
            }
        }
    }
}

// ===========================================================================
// Merged Q / Kh / VT launch: 1536 CTAs, segment decode.
//   seg 0: Q  = x @ Wq^T + bq        3-product -> hi/lo, col bias
//   seg 1: Kh = cos(y@Wkr^T + bkr)   3-product -> hi/lo, col bias
//   seg 2: VT[b] = WvT @ y[b]^T + bv PURE fp16 -> hi only, row bias
// ===========================================================================
__global__ __launch_bounds__(256, 2)
void gemmh_qkv(const __half* __restrict__ Xh, const __half* __restrict__ Xl,
               const __half* __restrict__ Yh, const __half* __restrict__ Yl,
               const __half* __restrict__ WqTh, const __half* __restrict__ WqTl,
               const __half* __restrict__ WkrTh, const __half* __restrict__ WkrTl,
               const __half* __restrict__ WvTh,
               const float* __restrict__ bq, const float* __restrict__ bkr,
               const float* __restrict__ bv,
               __half* __restrict__ Qh, __half* __restrict__ Ql,
               __half* __restrict__ Khh, __half* __restrict__ Khl,
               __half* __restrict__ VTh)
{
    const int SHB = 4 * ARR_HALFS * 2;
    extern __shared__ __half sm[];
    const uint32_t smb = smem_u32(sm);

    const int id  = blockIdx.x;
    const int seg = (id >= 1024) ? 2 : (id >> 9);
    const int lid = id - seg * 512;
    const bool p3 = (seg != 2);

    const __half *Ah, *Al, *Bh, *Bl;
    int m0, n0, Ncols;
    long cbase;
    if (seg == 2) {
        const int batch = lid >> 7;
        const int r = lid & 127;
        m0 = (r >> 4) * 128;
        n0 = (r & 15) * 128;
        Ah = WvTh; Al = WvTh;
        Bh = Yh + (long)batch * S_ * D_;
        Bl = Bh;
        Ncols = S_;
        cbase = (long)batch * D_ * S_;
    } else {
        m0 = (lid >> 3) * 128;
        n0 = (lid & 7) * 128;
        if (seg == 0) { Ah = Xh; Al = Xl; Bh = WqTh; Bl = WqTl; }
        else          { Ah = Yh; Al = Yl; Bh = WkrTh; Bl = WkrTl; }
        Ncols = D_;
        cbase = 0;
    }

    const int t    = threadIdx.x;
    const int lane = t & 31;
    const int w    = t >> 5;
    const int g    = lane >> 2;
    const int tg   = lane & 3;
    const int wm   = w & 1;
    const int wn   = w >> 1;

    const int KT = D_ / 32;

    auto stage_load = [&](int s, int kt) {
        const long kb = (long)kt * 32;
#pragma unroll
        for (int h = 0; h < 2; ++h) {
            const int c   = t + h * 256;
            const int row = c >> 2, q = c & 3;
            const int pq  = q ^ ((row >> 1) & 3);
            const uint32_t so = smb + (uint32_t)s * SHB + (uint32_t)(row * 32 + pq * 8) * 2;
            const long ga = (long)(m0 + row) * D_ + kb + q * 8;
            const long gb = (long)(n0 + row) * D_ + kb + q * 8;
            cpa16(so,         Ah + ga);
            cpa16(so + 16384, Bh + gb);
            if (p3) {
                cpa16(so + 8192,  Al + ga);
                cpa16(so + 24576, Bl + gb);
            }
        }
        cpa_commit();
    };

    const int sub = lane >> 3, l8 = lane & 7;
    const int a_csel = sub >> 1;
    const int a_moff = (sub & 1) * 8 + l8;
    const int b_csel = sub & 1;
    const int b_noff = (sub >> 1) * 8 + l8;

    uint32_t rA32[4], xqA[4];
#pragma unroll
    for (int mt = 0; mt < 4; ++mt) {
        const int row = wm * 64 + mt * 16 + a_moff;
        rA32[mt] = (uint32_t)row * 32;
        xqA[mt]  = (row >> 1) & 3;
    }
    uint32_t rB32[2], xqB[2];
#pragma unroll
    for (int np = 0; np < 2; ++np) {
        const int row = wn * 32 + np * 16 + b_noff;
        rB32[np] = (uint32_t)row * 32;
        xqB[np]  = (row >> 1) & 3;
    }

    float acc[4][4][4];
#pragma unroll
    for (int i = 0; i < 4; ++i)
#pragma unroll
        for (int j = 0; j < 4; ++j)
#pragma unroll
            for (int r = 0; r < 4; ++r) acc[i][j][r] = 0.f;

    stage_load(0, 0);
    stage_load(1, 1);

    for (int kt = 0; kt < KT; ++kt) {
        asm volatile("cp.async.wait_group 1;" ::: "memory");
        __syncthreads();
        if (kt + 2 < KT) stage_load((kt + 2) % 3, kt + 2);

        const uint32_t sAh = smb + (uint32_t)(kt % 3) * SHB;
        const uint32_t sAl = sAh + 8192;
        const uint32_t sBh = sAh + 16384;
        const uint32_t sBl = sAh + 24576;

#pragma unroll
        for (int ks = 0; ks < 2; ++ks) {
            const uint32_t qa = (uint32_t)(2 * ks + a_csel);
            const uint32_t qb = (uint32_t)(2 * ks + b_csel);

            uint32_t bh[4][2], bl[4][2];
#pragma unroll
            for (int np = 0; np < 2; ++np) {
                const uint32_t off = (rB32[np] + ((qb ^ xqB[np]) << 3)) * 2;
                uint32_t r[4];
                ldsm4(r, sBh + off);
                bh[np * 2][0] = r[0]; bh[np * 2][1] = r[1];
                bh[np * 2 + 1][0] = r[2]; bh[np * 2 + 1][1] = r[3];
                if (p3) {
                    ldsm4(r, sBl + off);
                    bl[np * 2][0] = r[0]; bl[np * 2][1] = r[1];
                    bl[np * 2 + 1][0] = r[2]; bl[np * 2 + 1][1] = r[3];
                }
            }
#pragma unroll
            for (int mt = 0; mt < 4; ++mt) {
                const uint32_t off = (rA32[mt] + ((qa ^ xqA[mt]) << 3)) * 2;
                uint32_t ah[4], al[4];
                ldsm4(ah, sAh + off);
                if (p3) ldsm4(al, sAl + off);
#pragma unroll
                for (int nt = 0; nt < 4; ++nt) {
                    mma16(acc[mt][nt], ah, bh[nt]);
                    if (p3) {
                        mma16(acc[mt][nt], al, bh[nt]);
                        mma16(acc[mt][nt], ah, bl[nt]);
                    }
                }
            }
        }
    }

    const float* bias = (seg == 0) ? bq : (seg == 1 ? bkr : bv);
    __half* Ch = (seg == 0) ? Qh : (seg == 1 ? Khh : VTh);
    __half* Cl = (seg == 0) ? Ql : Khl;

#pragma unroll
    for (int mt = 0; mt < 4; ++mt) {
#pragma unroll
        for (int nt = 0; nt < 4; ++nt) {
            const int r0 = m0 + wm * 64 + mt * 16 + g;
            const int c0 = n0 + wn * 32 + nt * 8 + 2 * tg;
            float b00, b01, b10, b11;
            if (seg == 2) {
                b00 = b01 = bias[r0];
                b10 = b11 = bias[r0 + 8];
            } else {
                b00 = b10 = bias[c0];
                b01 = b11 = bias[c0 + 1];
            }
            float v00 = acc[mt][nt][0] + b00;
            float v01 = acc[mt][nt][1] + b01;
            float v10 = acc[mt][nt][2] + b10;
            float v11 = acc[mt][nt][3] + b11;
            if (seg == 1) {
                v00 = __cosf(v00); v01 = __cosf(v01);
                v10 = __cosf(v10); v11 = __cosf(v11);
            }
            long o0 = cbase + (long)r0 * Ncols + c0;
            long o1 = o0 + 8L * Ncols;
            __half2 h0 = __floats2half2_rn(v00, v01);
            __half2 h1 = __floats2half2_rn(v10, v11);
            *(uint32_t*)(Ch + o0) = h2u(h0);
            *(uint32_t*)(Ch + o1) = h2u(h1);
            if (seg != 2) {
                __half2 l0 = __floats2half2_rn(v00 - __low2float(h0), v01 - __high2float(h0));
                __half2 l1 = __floats2half2_rn(v10 - __low2float(h1), v11 - __high2float(h1));
                *(uint32_t*)(Cl + o0) = h2u(l0);
                *(uint32_t*)(Cl + o1) = h2u(l1);
            }
        }
    }
}

// ===========================================================================
// out[b] = P[b] @ VT[b]^T — pure fp16, BK=64, 2-stage (R12-proven).
// ===========================================================================
__global__ __launch_bounds__(256, 2)
void gemmh_out(const __half* __restrict__ P, const __half* __restrict__ V,
               float* __restrict__ out)
{
    extern __shared__ __half sm[];
    const uint32_t smb = smem_u32(sm);

    const int z = blockIdx.z;
    P   += (long)z * S_ * S_;
    V   += (long)z * D_ * S_;
    out += (long)z * S_ * D_;

    const int m0 = blockIdx.y * 128;
    const int n0 = blockIdx.x * 128;
    const int t    = threadIdx.x;
    const int lane = t & 31;
    const int w    = t >> 5;
    const int g    = lane >> 2;
    const int tg   = lane & 3;
    const int wm   = w & 1;
    const int wn   = w >> 1;

    const int KT = S_ / 64;

    auto stage_load = [&](int s, int kt) {
        const long kb = (long)kt * 64;
#pragma unroll
        for (int h = 0; h < 4; ++h) {
            const int c   = t + h * 256;
            const int row = c >> 3, q = c & 7;
            const int pq  = q ^ (row & 7);
            const uint32_t so = smb + (uint32_t)s * 32768 + (uint32_t)(row * 64 + pq * 8) * 2;
            cpa16(so,         P + (long)(m0 + row) * S_ + kb + q * 8);
            cpa16(so + 16384, V + (long)(n0 + row) * S_ + kb + q * 8);
        }
        cpa_commit();
    };

    const int sub = lane >> 3, l8 = lane & 7;
    const int a_csel = sub >> 1;
    const int a_moff = (sub & 1) * 8 + l8;
    const int b_csel = sub & 1;
    const int b_noff = (sub >> 1) * 8 + l8;

    uint32_t rA64[4], xqA[4];
#pragma unroll
    for (int mt = 0; mt < 4; ++mt) {
        const int row = wm * 64 + mt * 16 + a_moff;
        rA64[mt] = (uint32_t)row * 64;
        xqA[mt]  = row & 7;
    }
    uint32_t rB64[2], xqB[2];
#pragma unroll
    for (int np = 0; np < 2; ++np) {
        const int row = wn * 32 + np * 16 + b_noff;
        rB64[np] = (uint32_t)row * 64;
        xqB[np]  = row & 7;
    }

    float acc[4][4][4];
#pragma unroll
    for (int i = 0; i < 4; ++i)
#pragma unroll
        for (int j = 0; j < 4; ++j)
#pragma unroll
            for (int r = 0; r < 4; ++r) acc[i][j][r] = 0.f;

    stage_load(0, 0);

    for (int kt = 0; kt < KT; ++kt) {
        asm volatile("cp.async.wait_group 0;" ::: "memory");
        __syncthreads();
        if (kt + 1 < KT) stage_load((kt + 1) & 1, kt + 1);

        const uint32_t sA = smb + (uint32_t)(kt & 1) * 32768;
        const uint32_t sB = sA + 16384;

#pragma unroll
        for (int ks = 0; ks < 4; ++ks) {
            const uint32_t qa = (uint32_t)(2 * ks + a_csel);
            const uint32_t qb = (uint32_t)(2 * ks + b_csel);

            uint32_t bh[4][2];
#pragma unroll
            for (int np = 0; np < 2; ++np) {
                const uint32_t off = (rB64[np] + ((qb ^ xqB[np]) << 3)) * 2;
                uint32_t r[4];
                ldsm4(r, sB + off);
                bh[np * 2][0] = r[0]; bh[np * 2][1] = r[1];
                bh[np * 2 + 1][0] = r[2]; bh[np * 2 + 1][1] = r[3];
            }
#pragma unroll
            for (int mt = 0; mt < 4; ++mt) {
                const uint32_t off = (rA64[mt] + ((qa ^ xqA[mt]) << 3)) * 2;
                uint32_t ah[4];
                ldsm4(ah, sA + off);
#pragma unroll
                for (int nt = 0; nt < 4; ++nt)
                    mma16(acc[mt][nt], ah, bh[nt]);
            }
        }
    }

#pragma unroll
    for (int mt = 0; mt < 4; ++mt) {
#pragma unroll
        for (int nt = 0; nt < 4; ++nt) {
            const int r0 = m0 + wm * 64 + mt * 16 + g;
            const int c0 = n0 + wn * 32 + nt * 8 + 2 * tg;
            long o0 = (long)r0 * D_ + c0;
            *(float2*)(out + o0)            = make_float2(acc[mt][nt][0], acc[mt][nt][1]);
            *(float2*)(out + o0 + 8L * D_)  = make_float2(acc[mt][nt][2], acc[mt][nt][3]);
        }
    }
}

// ===========================================================================
// fp32 -> (hi,lo) fp16 convert for x, y, Wk in ONE launch (y segments).
// y=0: x (8192 blk), y=1: y (8192 blk), y=2: Wk (first 1024 blk active)
// ===========================================================================
__global__ void conv_xyw(const float* __restrict__ x, __half* __restrict__ xh, __half* __restrict__ xl,
                         const float* __restrict__ y, __half* __restrict__ yh, __half* __restrict__ yl,
                         const float* __restrict__ wk, __half* __restrict__ wh, __half* __restrict__ wl)
{
    const float* src; __half *h, *l;
    if (blockIdx.y == 0)      { src = x;  h = xh; l = xl; }
    else if (blockIdx.y == 1) { src = y;  h = yh; l = yl; }
    else {
        if (blockIdx.x >= D_ * D_ / 1024) return;
        src = wk; h = wh; l = wl;
    }
    const long i = ((long)blockIdx.x * 256 + threadIdx.x) * 4;
    float4 v = *(const float4*)(src + i);
    __half2 h0 = __floats2half2_rn(v.x, v.y);
    __half2 h1 = __floats2half2_rn(v.z, v.w);
    __half2 l0 = __floats2half2_rn(v.x - __low2float(h0), v.y - __high2float(h0));
    __half2 l1 = __floats2half2_rn(v.z - __low2float(h1), v.w - __high2float(h1));
    *(uint2*)(h + i) = make_uint2(h2u(h0), h2u(h1));
    *(uint2*)(l + i) = make_uint2(h2u(l0), h2u(l1));
}

// ===========================================================================
// Sum 4 split-K fp32 partials -> hi/lo half pair.  D_*D_ elements.
// ===========================================================================
__global__ void combine4(const float* __restrict__ parts,
                         __half* __restrict__ dh, __half* __restrict__ dl)
{
    const long i = ((long)blockIdx.x * 256 + threadIdx.x) * 4;
    const long DD = (long)D_ * D_;
    float4 a = *(const float4*)(parts + i);
    float4 b = *(const float4*)(parts + DD + i);
    float4 c = *(const float4*)(parts + 2 * DD + i);
    float4 d = *(const float4*)(parts + 3 * DD + i);
    float4 v = make_float4(a.x + b.x + c.x + d.x, a.y + b.y + c.y + d.y,
                           a.z + b.z + c.z + d.z, a.w + b.w + c.w + d.w);
    __half2 h0 = __floats2half2_rn(v.x, v.y);
    __half2 h1 = __floats2half2_rn(v.z, v.w);
    __half2 l0 = __floats2half2_rn(v.x - __low2float(h0), v.y - __high2float(h0));
    __half2 l1 = __floats2half2_rn(v.z - __low2float(h1), v.w - __high2float(h1));
    *(uint2*)(dh + i) = make_uint2(h2u(h0), h2u(h1));
    *(uint2*)(dl + i) = make_uint2(h2u(l0), h2u(l1));
}

// ===========================================================================
// Transpose+convert for 3 square weights + bkr GEMV, ONE launch (z selects).
// ===========================================================================
__global__ void convT4(const float* __restrict__ s0, __half* __restrict__ d0h, __half* __restrict__ d0l,
                       const float* __restrict__ s1, __half* __restrict__ d1h, __half* __restrict__ d1l,
                       const float* __restrict__ s2, __half* __restrict__ d2h, __half* __restrict__ d2l,
                       const float* __restrict__ bk, const float* __restrict__ br,
                       float* __restrict__ bkr)
{
    const int x = threadIdx.x, yy = threadIdx.y;   // 32 x 8
    if (blockIdx.z == 3) {
        const int r = blockIdx.y * 32 + blockIdx.x;
        const int t = yy * 32 + x;
        float s = 0.f;
        for (int d = t; d < D_; d += 256)
            s += bk[d] * s0[(long)d * D_ + r];    // s0 = Wr
#pragma unroll
        for (int o = 16; o > 0; o >>= 1) s += __shfl_xor_sync(0xffffffffu, s, o);
        __shared__ float red[8];
        if ((t & 31) == 0) red[t >> 5] = s;
        __syncthreads();
        if (t == 0) {
            float ss = br[r];
            for (int i = 0; i < 8; ++i) ss += red[i];
            bkr[r] = ss;
        }
        return;
    }

    __shared__ float tile[32][33];
    const float* src; __half *dh, *dl;
    if (blockIdx.z == 0)      { src = s0; dh = d0h; dl = d0l; }
    else if (blockIdx.z == 1) { src = s1; dh = d1h; dl = d1l; }
    else                      { src = s2; dh = d2h; dl = d2l; }

    const int c0 = blockIdx.x * 32, r0 = blockIdx.y * 32;
#pragma unroll
    for (int j = 0; j < 32; j += 8)
        tile[yy + j][x] = src[(long)(r0 + yy + j) * D_ + c0 + x];
    __syncthreads();
#pragma unroll
    for (int j = 0; j < 32; j += 8) {
        float v = tile[x][yy + j];
        __half hh = __float2half_rn(v);
        long o = (long)(c0 + yy + j) * D_ + r0 + x;
        dh[o] = hh;
        dl[o] = __float2half_rn(v - __half2float(hh));
    }
}

// ---------------------------------------------------------------------------
// Row softmax over 2048 cols, summing two split-K partial buffers; fp16 out.
__global__ void softmax_rows2(const float* __restrict__ s0,
                              const float* __restrict__ s1,
                              __half* __restrict__ ph)
{
    const int NCOL = S_;
    const long ro = (long)blockIdx.x * NCOL;
    const int t = threadIdx.x;
    const int c8 = t * 8;

    __shared__ float red[8];

    float4 a0 = *(const float4*)(s0 + ro + c8);
    float4 a1 = *(const float4*)(s0 + ro + c8 + 4);
    float4 b0 = *(const float4*)(s1 + ro + c8);
    float4 b1 = *(const float4*)(s1 + ro + c8 + 4);
    float v[8] = { a0.x + b0.x, a0.y + b0.y, a0.z + b0.z, a0.w + b0.w,
                   a1.x + b1.x, a1.y + b1.y, a1.z + b1.z, a1.w + b1.w };

    float mx = v[0];
#pragma unroll
    for (int i = 1; i < 8; ++i) mx = fmaxf(mx, v[i]);
#pragma unroll
    for (int o = 16; o > 0; o >>= 1) mx = fmaxf(mx, __shfl_xor_sync(0xffffffffu, mx, o));
    if ((t & 31) == 0) red[t >> 5] = mx;
    __syncthreads();
    if (t == 0) {
        float m = red[0];
        for (int i = 1; i < 8; ++i) m = fmaxf(m, red[i]);
        red[0] = m;
    }
    __syncthreads();
    mx = red[0];

    float s = 0.f;
#pragma unroll
    for (int i = 0; i < 8; ++i) { v[i] = __expf(v[i] - mx); s += v[i]; }
#pragma unroll
    for (int o = 16; o > 0; o >>= 1) s += __shfl_xor_sync(0xffffffffu, s, o);
    __syncthreads();
    if ((t & 31) == 0) red[t >> 5] = s;
    __syncthreads();
    if (t == 0) {
        float ss = 0.f;
        for (int i = 0; i < 8; ++i) ss += red[i];
        red[0] = 1.f / ss;
    }
    __syncthreads();
    const float inv = red[0];

    uint32_t hw[4];
#pragma unroll
    for (int i = 0; i < 4; ++i)
        hw[i] = h2u(__floats2half2_rn(v[2 * i] * inv, v[2 * i + 1] * inv));
    *(uint4*)(ph + ro + c8) = make_uint4(hw[0], hw[1], hw[2], hw[3]);
}

// ---------------------------------------------------------------------------
extern "C" void kernel_launch(void* const* d_in, const int* in_sizes, int n_in,
                              void* d_out, int out_size)
{
    const float* x  = (const float*)d_in[0];
    const float* y  = (const float*)d_in[1];
    const float* Wq = (const float*)d_in[2];
    const float* bq = (const float*)d_in[3];
    const float* Wk = (const float*)d_in[4];
    const float* bk = (const float*)d_in[5];
    const float* Wv = (const float*)d_in[6];
    const float* bv = (const float*)d_in[7];
    const float* Wr = (const float*)d_in[8];
    const float* br = (const float*)d_in[9];
    float* out = (float*)d_out;

    __half *Xh, *Xl, *Yh, *Yl, *Qh, *Ql, *Khh, *Khl, *VTh, *Ph;
    __half *WrTh, *WrTl, *WqTh, *WqTl, *WvTh, *WvTl, *Wkh, *Wkl, *WkrTh, *WkrTl;
    float *Sc, *bkr;
    cudaGetSymbolAddress((void**)&Xh, g_Xh);   cudaGetSymbolAddress((void**)&Xl, g_Xl);
    cudaGetSymbolAddress((void**)&Yh, g_Yh);   cudaGetSymbolAddress((void**)&Yl, g_Yl);
    cudaGetSymbolAddress((void**)&Qh, g_Qh);   cudaGetSymbolAddress((void**)&Ql, g_Ql);
    cudaGetSymbolAddress((void**)&Khh, g_Khh); cudaGetSymbolAddress((void**)&Khl, g_Khl);
    cudaGetSymbolAddress((void**)&VTh, g_VTh);
    cudaGetSymbolAddress((void**)&Ph, g_Ph);
    cudaGetSymbolAddress((void**)&WrTh, g_WrTh); cudaGetSymbolAddress((void**)&WrTl, g_WrTl);
    cudaGetSymbolAddress((void**)&WqTh, g_WqTh); cudaGetSymbolAddress((void**)&WqTl, g_WqTl);
    cudaGetSymbolAddress((void**)&WvTh, g_WvTh); cudaGetSymbolAddress((void**)&WvTl, g_WvTl);
    cudaGetSymbolAddress((void**)&Wkh, g_Wkh);   cudaGetSymbolAddress((void**)&Wkl, g_Wkl);
    cudaGetSymbolAddress((void**)&WkrTh, g_WkrTh); cudaGetSymbolAddress((void**)&WkrTl, g_WkrTl);
    cudaGetSymbolAddress((void**)&Sc, g_S);
    cudaGetSymbolAddress((void**)&bkr, g_bkr);

    cudaFuncSetAttribute(gemmh<0,0,0>, cudaFuncAttributeMaxDynamicSharedMemorySize, SM3_BYTES);
    cudaFuncSetAttribute(gemmh_qkv, cudaFuncAttributeMaxDynamicSharedMemorySize, SM3_BYTES);
    cudaFuncSetAttribute(gemmh_out, cudaFuncAttributeMaxDynamicSharedMemorySize, SMO_BYTES);

    const long SBATCH = (long)S_ * S_;
    const long SHALF  = (long)B_ * S_ * S_;

    // 1) convert x, y, Wk in one launch (+ weights transpose & bkr in convT4)
    {
        dim3 g(BS_ * D_ / 1024, 3, 1);
        conv_xyw<<<g, 256>>>(x, Xh, Xl, y, Yh, Yl, Wk, Wkh, Wkl);
    }
    {
        dim3 g(D_ / 32, D_ / 32, 4);
        convT4<<<g, dim3(32, 8)>>>(Wr, WrTh, WrTl, Wq, WqTh, WqTl, Wv, WvTh, WvTl,
                                   bk, br, bkr);
    }

    // 2) WkrT = Wr^T @ Wk^T, split-K x4 into fp32 partials (in Sc scratch)
    {
        dim3 g(D_ / 128, D_ / 128, 4);
        gemmh<0,0,0><<<g, 256, SM3_BYTES>>>(WrTh, WrTl, Wkh, Wkl, nullptr,
                                            Sc, nullptr, nullptr,
                                            D_, D_, D_ / 4, D_, D_,
                                            0, 0, (long)D_ * D_, 0, 1);
    }
    combine4<<<D_ * D_ / 1024, 256>>>(Sc, WkrTh, WkrTl);

    // 3) merged Q + Kh + VT (1536 CTAs; VT pure fp16)
    gemmh_qkv<<<1536, 256, SM3_BYTES>>>(Xh, Xl, Yh, Yl,
                                        WqTh, WqTl, WkrTh, WkrTl, WvTh,
                                        bq, bkr, bv,
                                        Qh, Ql, Khh, Khl, VTh);

    // 4) scores[b] = Q[b] @ Kh[b]^T, split-K x2 -> two fp32 partial buffers
    {
        dim3 g(S_ / 128, S_ / 128, 2 * B_);
        gemmh<0,0,0><<<g, 256, SM3_BYTES>>>(Qh, Ql, Khh, Khl, nullptr,
                                            Sc, nullptr, nullptr,
                                            S_, S_, D_ / 2, D_, D_,
                                            (long)S_ * D_, (long)S_ * D_,
                                            SBATCH, SHALF, 2);
    }

    // 5) softmax rows (sums the two partials) -> probs fp16
    softmax_rows2<<<B_ * S_, 256>>>(Sc, Sc + SHALF, Ph);

    // 6) out[b] = P[b] @ VT[b]^T, pure fp16 BK=64 -> fp32
    {
        dim3 g(D_ / 128, S_ / 128, B_);
        gemmh_out<<<g, 256, SMO_BYTES>>>(Ph, VTh, out);
    }
}

// round 16
// speedup vs baseline: 1.0180x; 1.0177x over previous
#include <cuda_runtime.h>
#include <cuda_fp16.h>
#include <cstdint>
#include <math.h>

// Problem constants
#define B_  4
#define S_  2048
#define D_  1024
#define BS_ (B_ * S_)          // 8192

// ---------------- scratch (static device globals; no runtime allocation) ----
__device__ __half g_Xh[BS_ * D_], g_Xl[BS_ * D_];        // x hi/lo
__device__ __half g_Yh[BS_ * D_], g_Yl[BS_ * D_];        // y hi/lo
__device__ __half g_Qh[BS_ * D_], g_Ql[BS_ * D_];        // Q hi/lo
__device__ __half g_Khh[BS_ * D_], g_Khl[BS_ * D_];      // Kh hi/lo
__device__ __half g_VTh[BS_ * D_];                       // V^T per batch (fp16)
__device__ __half g_Ph[B_ * S_ * S_];                    // probs (fp16)
__device__ __half g_WrTh[D_ * D_], g_WrTl[D_ * D_];
__device__ __half g_WqTh[D_ * D_], g_WqTl[D_ * D_];
__device__ __half g_WvTh[D_ * D_];
__device__ __half g_WvTl[D_ * D_];                       // kept for convT4 symmetry
__device__ __half g_Wkh[D_ * D_], g_Wkl[D_ * D_];
__device__ __half g_WkrTh[D_ * D_], g_WkrTl[D_ * D_];
__device__ float  g_S[B_ * S_ * S_];   // scores fp32 (also WkrT split-K partials)
__device__ float  g_bkr[D_];

// ===========================================================================
__device__ __forceinline__ uint32_t h2u(__half2 h) {
    union { __half2 h; uint32_t u; } c; c.h = h; return c.u;
}

__device__ __forceinline__ void mma16(float* d, const uint32_t* a, const uint32_t* b) {
    asm volatile(
        "mma.sync.aligned.m16n8k16.row.col.f32.f16.f16.f32 "
        "{%0,%1,%2,%3}, {%4,%5,%6,%7}, {%8,%9}, {%0,%1,%2,%3};"
        : "+f"(d[0]), "+f"(d[1]), "+f"(d[2]), "+f"(d[3])
        : "r"(a[0]), "r"(a[1]), "r"(a[2]), "r"(a[3]),
          "r"(b[0]), "r"(b[1]));
}

__device__ __forceinline__ void ldsm4(uint32_t* r, uint32_t addr) {
    asm volatile("ldmatrix.sync.aligned.m8n8.x4.shared.b16 {%0,%1,%2,%3}, [%4];"
        : "=r"(r[0]), "=r"(r[1]), "=r"(r[2]), "=r"(r[3]) : "r"(addr));
}

__device__ __forceinline__ void cpa16(uint32_t dst, const void* src) {
    asm volatile("cp.async.cg.shared.global [%0], [%1], 16;" :: "r"(dst), "l"(src));
}
__device__ __forceinline__ void cpa_commit() {
    asm volatile("cp.async.commit_group;" ::: "memory");
}
__device__ __forceinline__ uint32_t smem_u32(const void* p) {
    uint32_t a;
    asm("{ .reg .u64 t; cvta.to.shared.u64 t, %1; cvt.u32.u64 %0, t; }"
        : "=r"(a) : "l"(p));
    return a;
}

#define ARR_HALFS 4096                       // 128x32 halves = 8KB
#define SM3_BYTES (3 * 4 * ARR_HALFS * 2)    // 96KB (3-product)
#define SMO_BYTES (2 * 32768)                // 64KB (out: BK=64, 2-stage)

// ===========================================================================
// fp16 tensor-core 3-product GEMM (R9-proven config): C[M,N]=op(A@B^T+bias)
// 128x128 block tile, BK=32, 3-stage cp.async, XOR-swizzle, ldmatrix.
// 8 warps (2M x 4N), warp tile 64x32, occ 2.
// ksplit: 0=none (z=batch), 1=z is k-chunk.
// ===========================================================================
template<int EPI_COS, int OUT_MODE, int ROW_BIAS>
__global__ __launch_bounds__(256, 2)
void gemmh(const __half* __restrict__ Ah, const __half* __restrict__ Al,
           const __half* __restrict__ Bh, const __half* __restrict__ Bl,
           const float* __restrict__ bias,
           float* __restrict__ C, __half* __restrict__ Ch, __half* __restrict__ Cl,
           int M, int N, int K, int lda, int ldb,
           long sA, long sB, long sC, int ksplit)
{
    const int SHB = 4 * ARR_HALFS * 2;
    extern __shared__ __half sm[];
    const uint32_t smb = smem_u32(sm);

    const int z = blockIdx.z;
    const int zb = ksplit ? 0 : z;
    Ah += (long)zb * sA;  Bh += (long)zb * sB;
    Al += (long)zb * sA;  Bl += (long)zb * sB;
    const long koff = ksplit ? (long)z * K : 0;
    const long cofs = (long)z * sC;

    const int m0 = blockIdx.y * 128;
    const int n0 = blockIdx.x * 128;
    const int t    = threadIdx.x;
    const int lane = t & 31;
    const int w    = t >> 5;
    const int g    = lane >> 2;
    const int tg   = lane & 3;
    const int wm   = w & 1;
    const int wn   = w >> 1;

    const int KT = K / 32;

    auto stage_load = [&](int s, int kt) {
        const long kb = koff + (long)kt * 32;
#pragma unroll
        for (int h = 0; h < 2; ++h) {
            const int c   = t + h * 256;
            const int row = c >> 2, q = c & 3;
            const int pq  = q ^ ((row >> 1) & 3);
            const uint32_t so = smb + (uint32_t)s * SHB + (uint32_t)(row * 32 + pq * 8) * 2;
            const long ga = (long)(m0 + row) * lda + kb + q * 8;
            const long gb = (long)(n0 + row) * ldb + kb + q * 8;
            cpa16(so,         Ah + ga);
            cpa16(so + 8192,  Al + ga);
            cpa16(so + 16384, Bh + gb);
            cpa16(so + 24576, Bl + gb);
        }
        cpa_commit();
    };

    const int sub = lane >> 3, l8 = lane & 7;
    const int a_csel = sub >> 1;
    const int a_moff = (sub & 1) * 8 + l8;
    const int b_csel = sub & 1;
    const int b_noff = (sub >> 1) * 8 + l8;

    uint32_t rA32[4], xqA[4];
#pragma unroll
    for (int mt = 0; mt < 4; ++mt) {
        const int row = wm * 64 + mt * 16 + a_moff;
        rA32[mt] = (uint32_t)row * 32;
        xqA[mt]  = (row >> 1) & 3;
    }
    uint32_t rB32[2], xqB[2];
#pragma unroll
    for (int np = 0; np < 2; ++np) {
        const int row = wn * 32 + np * 16 + b_noff;
        rB32[np] = (uint32_t)row * 32;
        xqB[np]  = (row >> 1) & 3;
    }

    float acc[4][4][4];
#pragma unroll
    for (int i = 0; i < 4; ++i)
#pragma unroll
        for (int j = 0; j < 4; ++j)
#pragma unroll
            for (int r = 0; r < 4; ++r) acc[i][j][r] = 0.f;

    stage_load(0, 0);
    stage_load(1, 1);

    for (int kt = 0; kt < KT; ++kt) {
        asm volatile("cp.async.wait_group 1;" ::: "memory");
        __syncthreads();
        if (kt + 2 < KT) stage_load((kt + 2) % 3, kt + 2);

        const uint32_t sAh = smb + (uint32_t)(kt % 3) * SHB;
        const uint32_t sAl = sAh + 8192;
        const uint32_t sBh = sAh + 16384;
        const uint32_t sBl = sAh + 24576;

#pragma unroll
        for (int ks = 0; ks < 2; ++ks) {
            const uint32_t qa = (uint32_t)(2 * ks + a_csel);
            const uint32_t qb = (uint32_t)(2 * ks + b_csel);

            uint32_t bh[4][2], bl[4][2];
#pragma unroll
            for (int np = 0; np < 2; ++np) {
                const uint32_t off = (rB32[np] + ((qb ^ xqB[np]) << 3)) * 2;
                uint32_t r[4];
                ldsm4(r, sBh + off);
                bh[np * 2][0] = r[0]; bh[np * 2][1] = r[1];
                bh[np * 2 + 1][0] = r[2]; bh[np * 2 + 1][1] = r[3];
                ldsm4(r, sBl + off);
                bl[np * 2][0] = r[0]; bl[np * 2][1] = r[1];
                bl[np * 2 + 1][0] = r[2]; bl[np * 2 + 1][1] = r[3];
            }
#pragma unroll
            for (int mt = 0; mt < 4; ++mt) {
                const uint32_t off = (rA32[mt] + ((qa ^ xqA[mt]) << 3)) * 2;
                uint32_t ah[4], al[4];
                ldsm4(ah, sAh + off);
                ldsm4(al, sAl + off);
#pragma unroll
                for (int nt = 0; nt < 4; ++nt) {
                    mma16(acc[mt][nt], ah, bh[nt]);
                    mma16(acc[mt][nt], al, bh[nt]);
                    mma16(acc[mt][nt], ah, bl[nt]);
                }
            }
        }
    }

#pragma unroll
    for (int mt = 0; mt < 4; ++mt) {
#pragma unroll
        for (int nt = 0; nt < 4; ++nt) {
            const int r0 = m0 + wm * 64 + mt * 16 + g;
            const int c0 = n0 + wn * 32 + nt * 8 + 2 * tg;
            float b00 = 0.f, b01 = 0.f, b10 = 0.f, b11 = 0.f;
            if (bias) {
                if (ROW_BIAS) {
                    b00 = b01 = bias[r0];
                    b10 = b11 = bias[r0 + 8];
                } else {
                    b00 = b10 = bias[c0];
                    b01 = b11 = bias[c0 + 1];
                }
            }
            float v00 = acc[mt][nt][0] + b00;
            float v01 = acc[mt][nt][1] + b01;
            float v10 = acc[mt][nt][2] + b10;
            float v11 = acc[mt][nt][3] + b11;
            if (EPI_COS) {
                v00 = cosf(v00); v01 = cosf(v01);
                v10 = cosf(v10); v11 = cosf(v11);
            }
            long o0 = cofs + (long)r0 * N + c0;
            long o1 = o0 + 8L * N;
            if (OUT_MODE == 1) {
                __half2 h0 = __floats2half2_rn(v00, v01);
                __half2 h1 = __floats2half2_rn(v10, v11);
                __half2 l0 = __floats2half2_rn(v00 - __low2float(h0), v01 - __high2float(h0));
                __half2 l1 = __floats2half2_rn(v10 - __low2float(h1), v11 - __high2float(h1));
                *(uint32_t*)(Ch + o0) = h2u(h0);
                *(uint32_t*)(Cl + o0) = h2u(l0);
                *(uint32_t*)(Ch + o1) = h2u(h1);
                *(uint32_t*)(Cl + o1) = h2u(l1);
            } else if (OUT_MODE == 2) {
                *(uint32_t*)(Ch + o0) = h2u(__floats2half2_rn(v00, v01));
                *(uint32_t*)(Ch + o1) = h2u(__floats2half2_rn(v10, v11));
            } else {
                *(float2*)(C + o0) = make_float2(v00, v01);
                *(float2*)(C + o1) = make_float2(v10, v11);
            }
        }
    }
}

// ===========================================================================
// Merged Q / Kh / VT launch: 1536 CTAs, segment decode.
//   seg 0: Q  = x @ Wq^T + bq        3-product -> hi/lo, col bias
//   seg 1: Kh = cos(y@Wkr^T + bkr)   3-product -> hi/lo, col bias
//   seg 2: VT[b] = WvT @ y[b]^T + bv PURE fp16 -> hi only, row bias
// ===========================================================================
__global__ __launch_bounds__(256, 2)
void gemmh_qkv(const __half* __restrict__ Xh, const __half* __restrict__ Xl,
               const __half* __restrict__ Yh, const __half* __restrict__ Yl,
               const __half* __restrict__ WqTh, const __half* __restrict__ WqTl,
               const __half* __restrict__ WkrTh, const __half* __restrict__ WkrTl,
               const __half* __restrict__ WvTh,
               const float* __restrict__ bq, const float* __restrict__ bkr,
               const float* __restrict__ bv,
               __half* __restrict__ Qh, __half* __restrict__ Ql,
               __half* __restrict__ Khh, __half* __restrict__ Khl,
               __half* __restrict__ VTh)
{
    const int SHB = 4 * ARR_HALFS * 2;
    extern __shared__ __half sm[];
    const uint32_t smb = smem_u32(sm);

    const int id  = blockIdx.x;
    const int seg = (id >= 1024) ? 2 : (id >> 9);
    const int lid = id - seg * 512;
    const bool p3 = (seg != 2);

    const __half *Ah, *Al, *Bh, *Bl;
    int m0, n0, Ncols;
    long cbase;
    if (seg == 2) {
        const int batch = lid >> 7;
        const int r = lid & 127;
        m0 = (r >> 4) * 128;
        n0 = (r & 15) * 128;
        Ah = WvTh; Al = WvTh;
        Bh = Yh + (long)batch * S_ * D_;
        Bl = Bh;
        Ncols = S_;
        cbase = (long)batch * D_ * S_;
    } else {
        m0 = (lid >> 3) * 128;
        n0 = (lid & 7) * 128;
        if (seg == 0) { Ah = Xh; Al = Xl; Bh = WqTh; Bl = WqTl; }
        else          { Ah = Yh; Al = Yl; Bh = WkrTh; Bl = WkrTl; }
        Ncols = D_;
        cbase = 0;
    }

    const int t    = threadIdx.x;
    const int lane = t & 31;
    const int w    = t >> 5;
    const int g    = lane >> 2;
    const int tg   = lane & 3;
    const int wm   = w & 1;
    const int wn   = w >> 1;

    const int KT = D_ / 32;

    auto stage_load = [&](int s, int kt) {
        const long kb = (long)kt * 32;
#pragma unroll
        for (int h = 0; h < 2; ++h) {
            const int c   = t + h * 256;
            const int row = c >> 2, q = c & 3;
            const int pq  = q ^ ((row >> 1) & 3);
            const uint32_t so = smb + (uint32_t)s * SHB + (uint32_t)(row * 32 + pq * 8) * 2;
            const long ga = (long)(m0 + row) * D_ + kb + q * 8;
            const long gb = (long)(n0 + row) * D_ + kb + q * 8;
            cpa16(so,         Ah + ga);
            cpa16(so + 16384, Bh + gb);
            if (p3) {
                cpa16(so + 8192,  Al + ga);
                cpa16(so + 24576, Bl + gb);
            }
        }
        cpa_commit();
    };

    const int sub = lane >> 3, l8 = lane & 7;
    const int a_csel = sub >> 1;
    const int a_moff = (sub & 1) * 8 + l8;
    const int b_csel = sub & 1;
    const int b_noff = (sub >> 1) * 8 + l8;

    uint32_t rA32[4], xqA[4];
#pragma unroll
    for (int mt = 0; mt < 4; ++mt) {
        const int row = wm * 64 + mt * 16 + a_moff;
        rA32[mt] = (uint32_t)row * 32;
        xqA[mt]  = (row >> 1) & 3;
    }
    uint32_t rB32[2], xqB[2];
#pragma unroll
    for (int np = 0; np < 2; ++np) {
        const int row = wn * 32 + np * 16 + b_noff;
        rB32[np] = (uint32_t)row * 32;
        xqB[np]  = (row >> 1) & 3;
    }

    float acc[4][4][4];
#pragma unroll
    for (int i = 0; i < 4; ++i)
#pragma unroll
        for (int j = 0; j < 4; ++j)
#pragma unroll
            for (int r = 0; r < 4; ++r) acc[i][j][r] = 0.f;

    stage_load(0, 0);
    stage_load(1, 1);

    for (int kt = 0; kt < KT; ++kt) {
        asm volatile("cp.async.wait_group 1;" ::: "memory");
        __syncthreads();
        if (kt + 2 < KT) stage_load((kt + 2) % 3, kt + 2);

        const uint32_t sAh = smb + (uint32_t)(kt % 3) * SHB;
        const uint32_t sAl = sAh + 8192;
        const uint32_t sBh = sAh + 16384;
        const uint32_t sBl = sAh + 24576;

#pragma unroll
        for (int ks = 0; ks < 2; ++ks) {
            const uint32_t qa = (uint32_t)(2 * ks + a_csel);
            const uint32_t qb = (uint32_t)(2 * ks + b_csel);

            uint32_t bh[4][2], bl[4][2];
#pragma unroll
            for (int np = 0; np < 2; ++np) {
                const uint32_t off = (rB32[np] + ((qb ^ xqB[np]) << 3)) * 2;
                uint32_t r[4];
                ldsm4(r, sBh + off);
                bh[np * 2][0] = r[0]; bh[np * 2][1] = r[1];
                bh[np * 2 + 1][0] = r[2]; bh[np * 2 + 1][1] = r[3];
                if (p3) {
                    ldsm4(r, sBl + off);
                    bl[np * 2][0] = r[0]; bl[np * 2][1] = r[1];
                    bl[np * 2 + 1][0] = r[2]; bl[np * 2 + 1][1] = r[3];
                }
            }
#pragma unroll
            for (int mt = 0; mt < 4; ++mt) {
                const uint32_t off = (rA32[mt] + ((qa ^ xqA[mt]) << 3)) * 2;
                uint32_t ah[4], al[4];
                ldsm4(ah, sAh + off);
                if (p3) ldsm4(al, sAl + off);
#pragma unroll
                for (int nt = 0; nt < 4; ++nt) {
                    mma16(acc[mt][nt], ah, bh[nt]);
                    if (p3) {
                        mma16(acc[mt][nt], al, bh[nt]);
                        mma16(acc[mt][nt], ah, bl[nt]);
                    }
                }
            }
        }
    }

    const float* bias = (seg == 0) ? bq : (seg == 1 ? bkr : bv);
    __half* Ch = (seg == 0) ? Qh : (seg == 1 ? Khh : VTh);
    __half* Cl = (seg == 0) ? Ql : Khl;

#pragma unroll
    for (int mt = 0; mt < 4; ++mt) {
#pragma unroll
        for (int nt = 0; nt < 4; ++nt) {
            const int r0 = m0 + wm * 64 + mt * 16 + g;
            const int c0 = n0 + wn * 32 + nt * 8 + 2 * tg;
            float b00, b01, b10, b11;
            if (seg == 2) {
                b00 = b01 = bias[r0];
                b10 = b11 = bias[r0 + 8];
            } else {
                b00 = b10 = bias[c0];
                b01 = b11 = bias[c0 + 1];
            }
            float v00 = acc[mt][nt][0] + b00;
            float v01 = acc[mt][nt][1] + b01;
            float v10 = acc[mt][nt][2] + b10;
            float v11 = acc[mt][nt][3] + b11;
            if (seg == 1) {
                v00 = cosf(v00); v01 = cosf(v01);
                v10 = cosf(v10); v11 = cosf(v11);
            }
            long o0 = cbase + (long)r0 * Ncols + c0;
            long o1 = o0 + 8L * Ncols;
            __half2 h0 = __floats2half2_rn(v00, v01);
            __half2 h1 = __floats2half2_rn(v10, v11);
            *(uint32_t*)(Ch + o0) = h2u(h0);
            *(uint32_t*)(Ch + o1) = h2u(h1);
            if (seg != 2) {
                __half2 l0 = __floats2half2_rn(v00 - __low2float(h0), v01 - __high2float(h0));
                __half2 l1 = __floats2half2_rn(v10 - __low2float(h1), v11 - __high2float(h1));
                *(uint32_t*)(Cl + o0) = h2u(l0);
                *(uint32_t*)(Cl + o1) = h2u(l1);
            }
        }
    }
}

// ===========================================================================
// out[b] = P[b] @ VT[b]^T — pure fp16, BK=64, 2-stage (R12-proven).
// ===========================================================================
__global__ __launch_bounds__(256, 2)
void gemmh_out(const __half* __restrict__ P, const __half* __restrict__ V,
               float* __restrict__ out)
{
    extern __shared__ __half sm[];
    const uint32_t smb = smem_u32(sm);

    const int z = blockIdx.z;
    P   += (long)z * S_ * S_;
    V   += (long)z * D_ * S_;
    out += (long)z * S_ * D_;

    const int m0 = blockIdx.y * 128;
    const int n0 = blockIdx.x * 128;
    const int t    = threadIdx.x;
    const int lane = t & 31;
    const int w    = t >> 5;
    const int g    = lane >> 2;
    const int tg   = lane & 3;
    const int wm   = w & 1;
    const int wn   = w >> 1;

    const int KT = S_ / 64;

    auto stage_load = [&](int s, int kt) {
        const long kb = (long)kt * 64;
#pragma unroll
        for (int h = 0; h < 4; ++h) {
            const int c   = t + h * 256;
            const int row = c >> 3, q = c & 7;
            const int pq  = q ^ (row & 7);
            const uint32_t so = smb + (uint32_t)s * 32768 + (uint32_t)(row * 64 + pq * 8) * 2;
            cpa16(so,         P + (long)(m0 + row) * S_ + kb + q * 8);
            cpa16(so + 16384, V + (long)(n0 + row) * S_ + kb + q * 8);
        }
        cpa_commit();
    };

    const int sub = lane >> 3, l8 = lane & 7;
    const int a_csel = sub >> 1;
    const int a_moff = (sub & 1) * 8 + l8;
    const int b_csel = sub & 1;
    const int b_noff = (sub >> 1) * 8 + l8;

    uint32_t rA64[4], xqA[4];
#pragma unroll
    for (int mt = 0; mt < 4; ++mt) {
        const int row = wm * 64 + mt * 16 + a_moff;
        rA64[mt] = (uint32_t)row * 64;
        xqA[mt]  = row & 7;
    }
    uint32_t rB64[2], xqB[2];
#pragma unroll
    for (int np = 0; np < 2; ++np) {
        const int row = wn * 32 + np * 16 + b_noff;
        rB64[np] = (uint32_t)row * 64;
        xqB[np]  = row & 7;
    }

    float acc[4][4][4];
#pragma unroll
    for (int i = 0; i < 4; ++i)
#pragma unroll
        for (int j = 0; j < 4; ++j)
#pragma unroll
            for (int r = 0; r < 4; ++r) acc[i][j][r] = 0.f;

    stage_load(0, 0);

    for (int kt = 0; kt < KT; ++kt) {
        asm volatile("cp.async.wait_group 0;" ::: "memory");
        __syncthreads();
        if (kt + 1 < KT) stage_load((kt + 1) & 1, kt + 1);

        const uint32_t sA = smb + (uint32_t)(kt & 1) * 32768;
        const uint32_t sB = sA + 16384;

#pragma unroll
        for (int ks = 0; ks < 4; ++ks) {
            const uint32_t qa = (uint32_t)(2 * ks + a_csel);
            const uint32_t qb = (uint32_t)(2 * ks + b_csel);

            uint32_t bh[4][2];
#pragma unroll
            for (int np = 0; np < 2; ++np) {
                const uint32_t off = (rB64[np] + ((qb ^ xqB[np]) << 3)) * 2;
                uint32_t r[4];
                ldsm4(r, sB + off);
                bh[np * 2][0] = r[0]; bh[np * 2][1] = r[1];
                bh[np * 2 + 1][0] = r[2]; bh[np * 2 + 1][1] = r[3];
            }
#pragma unroll
            for (int mt = 0; mt < 4; ++mt) {
                const uint32_t off = (rA64[mt] + ((qa ^ xqA[mt]) << 3)) * 2;
                uint32_t ah[4];
                ldsm4(ah, sA + off);
#pragma unroll
                for (int nt = 0; nt < 4; ++nt)
                    mma16(acc[mt][nt], ah, bh[nt]);
            }
        }
    }

#pragma unroll
    for (int mt = 0; mt < 4; ++mt) {
#pragma unroll
        for (int nt = 0; nt < 4; ++nt) {
            const int r0 = m0 + wm * 64 + mt * 16 + g;
            const int c0 = n0 + wn * 32 + nt * 8 + 2 * tg;
            long o0 = (long)r0 * D_ + c0;
            *(float2*)(out + o0)            = make_float2(acc[mt][nt][0], acc[mt][nt][1]);
            *(float2*)(out + o0 + 8L * D_)  = make_float2(acc[mt][nt][2], acc[mt][nt][3]);
        }
    }
}

// ===========================================================================
// fp32 -> (hi,lo) fp16 converts (R13 configuration)
// ===========================================================================
__global__ void conv_xy(const float* __restrict__ x, __half* __restrict__ xh, __half* __restrict__ xl,
                        const float* __restrict__ y, __half* __restrict__ yh, __half* __restrict__ yl)
{
    const float* src = blockIdx.y ? y : x;
    __half* h = blockIdx.y ? yh : xh;
    __half* l = blockIdx.y ? yl : xl;
    const long i = ((long)blockIdx.x * 256 + threadIdx.x) * 4;
    float4 v = *(const float4*)(src + i);
    __half2 h0 = __floats2half2_rn(v.x, v.y);
    __half2 h1 = __floats2half2_rn(v.z, v.w);
    __half2 l0 = __floats2half2_rn(v.x - __low2float(h0), v.y - __high2float(h0));
    __half2 l1 = __floats2half2_rn(v.z - __low2float(h1), v.w - __high2float(h1));
    *(uint2*)(h + i) = make_uint2(h2u(h0), h2u(h1));
    *(uint2*)(l + i) = make_uint2(h2u(l0), h2u(l1));
}

__global__ void conv_hl(const float* __restrict__ src,
                        __half* __restrict__ h, __half* __restrict__ l)
{
    const long i = ((long)blockIdx.x * 256 + threadIdx.x) * 4;
    float4 v = *(const float4*)(src + i);
    __half2 h0 = __floats2half2_rn(v.x, v.y);
    __half2 h1 = __floats2half2_rn(v.z, v.w);
    __half2 l0 = __floats2half2_rn(v.x - __low2float(h0), v.y - __high2float(h0));
    __half2 l1 = __floats2half2_rn(v.z - __low2float(h1), v.w - __high2float(h1));
    *(uint2*)(h + i) = make_uint2(h2u(h0), h2u(h1));
    *(uint2*)(l + i) = make_uint2(h2u(l0), h2u(l1));
}

// ===========================================================================
// Sum 4 split-K fp32 partials -> hi/lo half pair.  D_*D_ elements.
// ===========================================================================
__global__ void combine4(const float* __restrict__ parts,
                         __half* __restrict__ dh, __half* __restrict__ dl)
{
    const long i = ((long)blockIdx.x * 256 + threadIdx.x) * 4;
    const long DD = (long)D_ * D_;
    float4 a = *(const float4*)(parts + i);
    float4 b = *(const float4*)(parts + DD + i);
    float4 c = *(const float4*)(parts + 2 * DD + i);
    float4 d = *(const float4*)(parts + 3 * DD + i);
    float4 v = make_float4(a.x + b.x + c.x + d.x, a.y + b.y + c.y + d.y,
                           a.z + b.z + c.z + d.z, a.w + b.w + c.w + d.w);
    __half2 h0 = __floats2half2_rn(v.x, v.y);
    __half2 h1 = __floats2half2_rn(v.z, v.w);
    __half2 l0 = __floats2half2_rn(v.x - __low2float(h0), v.y - __high2float(h0));
    __half2 l1 = __floats2half2_rn(v.z - __low2float(h1), v.w - __high2float(h1));
    *(uint2*)(dh + i) = make_uint2(h2u(h0), h2u(h1));
    *(uint2*)(dl + i) = make_uint2(h2u(l0), h2u(l1));
}

// ===========================================================================
// Transpose+convert for 3 square weights + bkr GEMV, ONE launch (z selects).
// ===========================================================================
__global__ void convT4(const float* __restrict__ s0, __half* __restrict__ d0h, __half* __restrict__ d0l,
                       const float* __restrict__ s1, __half* __restrict__ d1h, __half* __restrict__ d1l,
                       const float* __restrict__ s2, __half* __restrict__ d2h, __half* __restrict__ d2l,
                       const float* __restrict__ bk, const float* __restrict__ br,
                       float* __restrict__ bkr)
{
    const int x = threadIdx.x, yy = threadIdx.y;   // 32 x 8
    if (blockIdx.z == 3) {
        const int r = blockIdx.y * 32 + blockIdx.x;
        const int t = yy * 32 + x;
        float s = 0.f;
        for (int d = t; d < D_; d += 256)
            s += bk[d] * s0[(long)d * D_ + r];    // s0 = Wr
#pragma unroll
        for (int o = 16; o > 0; o >>= 1) s += __shfl_xor_sync(0xffffffffu, s, o);
        __shared__ float red[8];
        if ((t & 31) == 0) red[t >> 5] = s;
        __syncthreads();
        if (t == 0) {
            float ss = br[r];
            for (int i = 0; i < 8; ++i) ss += red[i];
            bkr[r] = ss;
        }
        return;
    }

    __shared__ float tile[32][33];
    const float* src; __half *dh, *dl;
    if (blockIdx.z == 0)      { src = s0; dh = d0h; dl = d0l; }
    else if (blockIdx.z == 1) { src = s1; dh = d1h; dl = d1l; }
    else                      { src = s2; dh = d2h; dl = d2l; }

    const int c0 = blockIdx.x * 32, r0 = blockIdx.y * 32;
#pragma unroll
    for (int j = 0; j < 32; j += 8)
        tile[yy + j][x] = src[(long)(r0 + yy + j) * D_ + c0 + x];
    __syncthreads();
#pragma unroll
    for (int j = 0; j < 32; j += 8) {
        float v = tile[x][yy + j];
        __half hh = __float2half_rn(v);
        long o = (long)(c0 + yy + j) * D_ + r0 + x;
        dh[o] = hh;
        dl[o] = __float2half_rn(v - __half2float(hh));
    }
}

// ---------------------------------------------------------------------------
// Row softmax over 2048 cols; 8 contiguous cols/thread; fp16 out.
__global__ void softmax_rows(const float* __restrict__ scores,
                             __half* __restrict__ ph)
{
    const int NCOL = S_;
    const float* p = scores + (long)blockIdx.x * NCOL;
    const int t = threadIdx.x;
    const int c8 = t * 8;

    __shared__ float red[8];

    float4 va = *(const float4*)(p + c8);
    float4 vb = *(const float4*)(p + c8 + 4);
    float v[8] = { va.x, va.y, va.z, va.w, vb.x, vb.y, vb.z, vb.w };

    float mx = v[0];
#pragma unroll
    for (int i = 1; i < 8; ++i) mx = fmaxf(mx, v[i]);
#pragma unroll
    for (int o = 16; o > 0; o >>= 1) mx = fmaxf(mx, __shfl_xor_sync(0xffffffffu, mx, o));
    if ((t & 31) == 0) red[t >> 5] = mx;
    __syncthreads();
    if (t == 0) {
        float m = red[0];
        for (int i = 1; i < 8; ++i) m = fmaxf(m, red[i]);
        red[0] = m;
    }
    __syncthreads();
    mx = red[0];

    float s = 0.f;
#pragma unroll
    for (int i = 0; i < 8; ++i) { v[i] = expf(v[i] - mx); s += v[i]; }
#pragma unroll
    for (int o = 16; o > 0; o >>= 1) s += __shfl_xor_sync(0xffffffffu, s, o);
    __syncthreads();
    if ((t & 31) == 0) red[t >> 5] = s;
    __syncthreads();
    if (t == 0) {
        float ss = 0.f;
        for (int i = 0; i < 8; ++i) ss += red[i];
        red[0] = 1.f / ss;
    }
    __syncthreads();
    const float inv = red[0];

    uint32_t hw[4];
#pragma unroll
    for (int i = 0; i < 4; ++i)
        hw[i] = h2u(__floats2half2_rn(v[2 * i] * inv, v[2 * i + 1] * inv));
    *(uint4*)(ph + (long)blockIdx.x * NCOL + c8) = make_uint4(hw[0], hw[1], hw[2], hw[3]);
}

// ---------------------------------------------------------------------------
extern "C" void kernel_launch(void* const* d_in, const int* in_sizes, int n_in,
                              void* d_out, int out_size)
{
    const float* x  = (const float*)d_in[0];
    const float* y  = (const float*)d_in[1];
    const float* Wq = (const float*)d_in[2];
    const float* bq = (const float*)d_in[3];
    const float* Wk = (const float*)d_in[4];
    const float* bk = (const float*)d_in[5];
    const float* Wv = (const float*)d_in[6];
    const float* bv = (const float*)d_in[7];
    const float* Wr = (const float*)d_in[8];
    const float* br = (const float*)d_in[9];
    float* out = (float*)d_out;

    __half *Xh, *Xl, *Yh, *Yl, *Qh, *Ql, *Khh, *Khl, *VTh, *Ph;
    __half *WrTh, *WrTl, *WqTh, *WqTl, *WvTh, *WvTl, *Wkh, *Wkl, *WkrTh, *WkrTl;
    float *Sc, *bkr;
    cudaGetSymbolAddress((void**)&Xh, g_Xh);   cudaGetSymbolAddress((void**)&Xl, g_Xl);
    cudaGetSymbolAddress((void**)&Yh, g_Yh);   cudaGetSymbolAddress((void**)&Yl, g_Yl);
    cudaGetSymbolAddress((void**)&Qh, g_Qh);   cudaGetSymbolAddress((void**)&Ql, g_Ql);
    cudaGetSymbolAddress((void**)&Khh, g_Khh); cudaGetSymbolAddress((void**)&Khl, g_Khl);
    cudaGetSymbolAddress((void**)&VTh, g_VTh);
    cudaGetSymbolAddress((void**)&Ph, g_Ph);
    cudaGetSymbolAddress((void**)&WrTh, g_WrTh); cudaGetSymbolAddress((void**)&WrTl, g_WrTl);
    cudaGetSymbolAddress((void**)&WqTh, g_WqTh); cudaGetSymbolAddress((void**)&WqTl, g_WqTl);
    cudaGetSymbolAddress((void**)&WvTh, g_WvTh); cudaGetSymbolAddress((void**)&WvTl, g_WvTl);
    cudaGetSymbolAddress((void**)&Wkh, g_Wkh);   cudaGetSymbolAddress((void**)&Wkl, g_Wkl);
    cudaGetSymbolAddress((void**)&WkrTh, g_WkrTh); cudaGetSymbolAddress((void**)&WkrTl, g_WkrTl);
    cudaGetSymbolAddress((void**)&Sc, g_S);
    cudaGetSymbolAddress((void**)&bkr, g_bkr);

    cudaFuncSetAttribute(gemmh<0,0,0>, cudaFuncAttributeMaxDynamicSharedMemorySize, SM3_BYTES);
    cudaFuncSetAttribute(gemmh_qkv, cudaFuncAttributeMaxDynamicSharedMemorySize, SM3_BYTES);
    cudaFuncSetAttribute(gemmh_out, cudaFuncAttributeMaxDynamicSharedMemorySize, SMO_BYTES);

    // 1) convert inputs / weights (+ bkr fused into convT4 z=3)
    {
        dim3 g(BS_ * D_ / 1024, 2, 1);
        conv_xy<<<g, 256>>>(x, Xh, Xl, y, Yh, Yl);
    }
    conv_hl<<<D_ * D_ / 1024, 256>>>(Wk, Wkh, Wkl);
    {
        dim3 g(D_ / 32, D_ / 32, 4);
        convT4<<<g, dim3(32, 8)>>>(Wr, WrTh, WrTl, Wq, WqTh, WqTl, Wv, WvTh, WvTl,
                                   bk, br, bkr);
    }

    // 2) WkrT = Wr^T @ Wk^T, split-K x4 into fp32 partials (in Sc scratch)
    {
        dim3 g(D_ / 128, D_ / 128, 4);
        gemmh<0,0,0><<<g, 256, SM3_BYTES>>>(WrTh, WrTl, Wkh, Wkl, nullptr,
                                            Sc, nullptr, nullptr,
                                            D_, D_, D_ / 4, D_, D_,
                                            0, 0, (long)D_ * D_, 1);
    }
    combine4<<<D_ * D_ / 1024, 256>>>(Sc, WkrTh, WkrTl);

    // 3) merged Q + Kh + VT (1536 CTAs; VT pure fp16)
    gemmh_qkv<<<1536, 256, SM3_BYTES>>>(Xh, Xl, Yh, Yl,
                                        WqTh, WqTl, WkrTh, WkrTl, WvTh,
                                        bq, bkr, bv,
                                        Qh, Ql, Khh, Khl, VTh);

    // 4) scores[b] = Q[b] @ Kh[b]^T -> fp32 (single pass, full K)
    {
        dim3 g(S_ / 128, S_ / 128, B_);
        gemmh<0,0,0><<<g, 256, SM3_BYTES>>>(Qh, Ql, Khh, Khl, nullptr,
                                            Sc, nullptr, nullptr,
                                            S_, S_, D_, D_, D_,
                                            (long)S_ * D_, (long)S_ * D_,
                                            (long)S_ * S_, 0);
    }

    // 5) softmax rows -> probs fp16
    softmax_rows<<<B_ * S_, 256>>>(Sc, Ph);

    // 6) out[b] = P[b] @ VT[b]^T, pure fp16 BK=64 -> fp32
    {
        dim3 g(D_ / 128, S_ / 128, B_);
        gemmh_out<<<g, 256, SMO_BYTES>>>(Ph, VTh, out);
    }
}